// round 10
// baseline (speedup 1.0000x reference)
#include <cuda_runtime.h>
#include <math.h>
#include <stdint.h>

#define BB   256
#define DM   100
#define LLEN 415
#define LGG  411
#define PP   411
#define NF   100
#define NCLS 2987

// ---------------- scratch (device globals; no allocation) ----------------
__device__ float    d_Asum[BB * LLEN];
__device__ float    d_Tsum[BB * LLEN];
__device__ float    d_cmp[PP];
__device__ float    d_tw[BB * DM];
__device__ unsigned d_pooled[BB * 300];
__device__ float    d_combine[BB * 200];
__device__ float    d_hidden[BB * 400];

// packed f32x2 FMA
__device__ __forceinline__ unsigned long long ffma2(unsigned long long a,
                                                    unsigned long long b,
                                                    unsigned long long c) {
    unsigned long long d;
    asm("fma.rn.f32x2 %0, %1, %2, %3;" : "=l"(d) : "l"(a), "l"(b), "l"(c));
    return d;
}
__device__ __forceinline__ float acc2_sum(unsigned long long a) {
    return __uint_as_float((unsigned)(a & 0xffffffffull)) +
           __uint_as_float((unsigned)(a >> 32));
}
// pack (lo, hi) floats -> bf16x2
__device__ __forceinline__ uint32_t pack_bf16(float lo, float hi) {
    uint32_t r;
    asm("cvt.rn.bf16x2.f32 %0, %1, %2;" : "=r"(r) : "f"(hi), "f"(lo));
    return r;
}
__device__ __forceinline__ void mma16n8k16(float* c, uint32_t a0, uint32_t a1,
                                           uint32_t a2, uint32_t a3,
                                           uint32_t b0, uint32_t b1) {
    asm volatile(
        "mma.sync.aligned.m16n8k16.row.col.f32.bf16.bf16.f32 "
        "{%0,%1,%2,%3}, {%4,%5,%6,%7}, {%8,%9}, {%0,%1,%2,%3};"
        : "+f"(c[0]), "+f"(c[1]), "+f"(c[2]), "+f"(c[3])
        : "r"(a0), "r"(a1), "r"(a2), "r"(a3), "r"(b0), "r"(b1));
}
__device__ __forceinline__ int dec_g(int q) {
    return (q < 7) ? 0 : (q < 21) ? 1 : 2;
}

// ---------------- K1: per-token Asum + row-sum ----------------
__global__ void k_token(const int* __restrict__ ltext, const float* __restrict__ emb,
                        const float* __restrict__ att_w, const float* __restrict__ att_b) {
    int warp = (blockIdx.x * blockDim.x + threadIdx.x) >> 5;
    int lane = threadIdx.x & 31;
    if (warp >= BB * LLEN) return;
    int tok = ltext[warp];
    const float* er = emb + (long)tok * DM;
    float s[5] = {0.f, 0.f, 0.f, 0.f, 0.f};
    float ts = 0.f;
    for (int d = lane; d < DM; d += 32) {
        float e = er[d];
        ts += e;
        s[0] += e * att_w[0 * DM + d];
        s[1] += e * att_w[1 * DM + d];
        s[2] += e * att_w[2 * DM + d];
        s[3] += e * att_w[3 * DM + d];
        s[4] += e * att_w[4 * DM + d];
    }
    #pragma unroll
    for (int o = 16; o > 0; o >>= 1) {
        #pragma unroll
        for (int w = 0; w < 5; ++w) s[w] += __shfl_down_sync(0xffffffffu, s[w], o);
        ts += __shfl_down_sync(0xffffffffu, ts, o);
    }
    if (lane == 0) {
        float a = 0.f;
        #pragma unroll
        for (int w = 0; w < 5; ++w) a += tanhf(s[w] + att_b[w]);
        d_Asum[warp] = a;
        d_Tsum[warp] = ts;
    }
}

// ---------------- K2: comparison[p] ----------------
__global__ void k_cmp() {
    __shared__ float smn[256], smx[256];
    int p = blockIdx.x;
    int b = threadIdx.x;
    const float* a = d_Asum + b * LLEN + p;
    float mn = a[0], mx = a[0];
    #pragma unroll
    for (int w = 1; w < 5; ++w) { float v = a[w]; mn = fminf(mn, v); mx = fmaxf(mx, v); }
    smn[b] = mn; smx[b] = mx;
    __syncthreads();
    for (int sft = 128; sft > 0; sft >>= 1) {
        if (b < sft) {
            smn[b] = fminf(smn[b], smn[b + sft]);
            smx[b] = fmaxf(smx[b], smx[b + sft]);
        }
        __syncthreads();
    }
    if (b == 0) d_cmp[p] = 0.8f * smn[0] + 0.8f * smx[0];
}

// ---------------- K3: judge + scan (fp32-exact truncation) ----------------
#define SCAN_KEEP 64
#define SCAN_START (PP - SCAN_KEEP)
__global__ void k_scan(const int* __restrict__ ltext, const float* __restrict__ emb) {
    __shared__ int   toks[SCAN_KEEP];
    __shared__ float jflag[SCAN_KEEP];
    int b = blockIdx.x, tid = threadIdx.x;
    if (tid < SCAN_KEEP) {
        int p = SCAN_START + tid;
        toks[tid]  = ltext[b * LLEN + p + 2];
        jflag[tid] = (d_Tsum[b * LLEN + p + 2] > d_cmp[p]) ? 1.f : 0.f;
    }
    __syncthreads();
    if (tid >= DM) return;
    const float r = 1.0f / 411.0f;
    float tw = 0.f;
    #pragma unroll 8
    for (int i = 0; i < SCAN_KEEP; ++i) {
        float e = emb[(long)toks[i] * DM + tid] * jflag[i];
        tw = (tw + e) * r;
    }
    d_tw[b * DM + tid] = tw;
}

// ---------------- K4: local_units ----------------
__global__ void k_local(const float* __restrict__ att2_w, const float* __restrict__ att2_b) {
    __shared__ float twr[DM];
    int b = blockIdx.x, tid = threadIdx.x;
    if (tid < DM) twr[tid] = d_tw[b * DM + tid];
    __syncthreads();
    if (tid >= DM) return;
    float acc = att2_b[tid];
    const float* wr = att2_w + tid * DM;
    #pragma unroll 4
    for (int d = 0; d < DM; ++d) acc += twr[d] * wr[d];
    d_combine[b * 200 + tid] = acc;
}

// ---------------- zero pooled ----------------
__global__ void k_zero() {
    int i = blockIdx.x * blockDim.x + threadIdx.x;
    if (i < BB * 300) d_pooled[i] = 0u;
}

// ---------------- K5: conv via mma.sync bf16 (m16n8k16), m32 per warp ----
// Per CTA: batch b, 96-t tile (+2 halo), 104 f (13 n-tiles), 3 warps x m32
// (two m16 tiles each). Per slice per warp: 4 A LDS.64 + 13 B LDS.64 ->
// 26 MMAs (0.65 loads/MMA, ~1.8x less LDS than R9). EP2=56 u32/row makes
// A-frag LDS.64 conflict-free (quad banks 0/24/16/8 + col 0/2/4/6).
#define EP2 56
__global__ void __launch_bounds__(96, 4) k_conv_mma(
    const int* __restrict__ gtext, const float* __restrict__ emb,
    const float* __restrict__ w1, const float* __restrict__ cb1,
    const float* __restrict__ w2, const float* __restrict__ cb2,
    const float* __restrict__ w3, const float* __restrict__ cb3) {
    __shared__ __align__(16) uint32_t EgS[98 * EP2];   // 21952 B
    __shared__ __align__(16) uint32_t Bs[832];         // 3328 B
    __shared__ float sBias[3][104];                    // 1248 B
    int tid = threadIdx.x, lane = tid & 31, wid = tid >> 5;
    int t0 = blockIdx.x * 96, b = blockIdx.y;

    const float* ws[3] = {w1, w2, w3};
    const float* cbs[3] = {cb1, cb2, cb3};

    for (int u = tid; u < 312; u += 96) {
        int g = u / 104, f = u - g * 104;
        sBias[g][f] = (f < 100) ? cbs[g][f] : 0.f;
    }
    // E tile rows t0..t0+97 as bf16x2, pair-interleaved within 8-pair blocks
    for (int r = wid; r < 98; r += 3) {
        int gt = t0 + r;
        const float* er = (gt < LGG) ? emb + (long)gtext[b * LGG + gt] * DM : 0;
        for (int q = lane; q < EP2; q += 32) {
            int c0 = 2 * q;
            float v0 = (er && c0 < 100) ? er[c0] : 0.f;
            float v1 = (er && c0 + 1 < 100) ? er[c0 + 1] : 0.f;
            int bq = q & 7;
            int p = (bq < 4) ? 2 * bq : 2 * (bq - 4) + 1;
            EgS[r * EP2 + (q & ~7) + p] = pack_bf16(v0, v1);
        }
    }

    // Prefetch a W slice (832 bf16x2) into registers: 9 per thread (96 thr).
    uint32_t rw[9];
    {
        #pragma unroll
        for (int j = 0; j < 9; ++j) {
            int idx = tid + 96 * j;
            uint32_t v = 0u;
            if (idx < 832) {
                int nt = idx >> 6, rem = idx & 63, ni = rem >> 3, p = rem & 7;
                int qq = (p & 1) ? (p >> 1) + 4 : (p >> 1);
                int k0 = 2 * qq;
                int f = nt * 8 + ni;
                float v0 = (f < 100 && k0 < 100) ? w1[f * 100 + k0] : 0.f;
                float v1 = (f < 100 && k0 + 1 < 100) ? w1[f * 100 + k0 + 1] : 0.f;
                v = pack_bf16(v0, v1);
            }
            rw[j] = v;
        }
    }

    int q = 0;
    for (int g = 0; g < 3; ++g) {
        float acc[2][13][4];
        #pragma unroll
        for (int tt = 0; tt < 2; ++tt)
            #pragma unroll
            for (int nt = 0; nt < 13; ++nt)
                #pragma unroll
                for (int j = 0; j < 4; ++j) acc[tt][nt][j] = 0.f;
        int ns = (g + 1) * 7;
        for (int i = 0; i < ns; ++i, ++q) {
            __syncthreads();
            #pragma unroll
            for (int j = 0; j < 9; ++j) {
                int idx = tid + 96 * j;
                if (idx < 832) Bs[idx] = rw[j];
            }
            __syncthreads();
            if (q + 1 < 42) {                  // prefetch next slice under MMA
                int qn = q + 1;
                int gn = dec_g(qn);
                int base = (gn == 0) ? 0 : (gn == 1) ? 7 : 21;
                int ii = qn - base;
                int sn = ii / 7, ksn = ii - sn * 7;
                int Kg = (gn + 1) * 100;
                const float* w = ws[gn];
                #pragma unroll
                for (int j = 0; j < 9; ++j) {
                    int idx = tid + 96 * j;
                    uint32_t v = 0u;
                    if (idx < 832) {
                        int nt = idx >> 6, rem = idx & 63, ni = rem >> 3, p = rem & 7;
                        int qq = (p & 1) ? (p >> 1) + 4 : (p >> 1);
                        int k0 = ksn * 16 + 2 * qq;
                        int f = nt * 8 + ni;
                        float v0 = (f < 100 && k0 < 100) ? w[f * Kg + sn * 100 + k0] : 0.f;
                        float v1 = (f < 100 && k0 + 1 < 100) ? w[f * Kg + sn * 100 + k0 + 1] : 0.f;
                        v = pack_bf16(v0, v1);
                    }
                    rw[j] = v;
                }
            }
            int s = i / 7, ks = i - s * 7;
            int r0 = wid * 32 + (lane >> 2) + s;
            int ab = ks * 8 + 2 * (lane & 3);
            uint2 a0Lo = *reinterpret_cast<const uint2*>(&EgS[r0 * EP2 + ab]);
            uint2 a0Hi = *reinterpret_cast<const uint2*>(&EgS[(r0 + 8) * EP2 + ab]);
            uint2 a1Lo = *reinterpret_cast<const uint2*>(&EgS[(r0 + 16) * EP2 + ab]);
            uint2 a1Hi = *reinterpret_cast<const uint2*>(&EgS[(r0 + 24) * EP2 + ab]);
            const uint32_t* bp = &Bs[(lane >> 2) * 8 + 2 * (lane & 3)];
            #pragma unroll
            for (int nt = 0; nt < 13; ++nt) {
                uint2 bv = *reinterpret_cast<const uint2*>(bp + nt * 64);
                mma16n8k16(acc[0][nt], a0Lo.x, a0Hi.x, a0Lo.y, a0Hi.y, bv.x, bv.y);
                mma16n8k16(acc[1][nt], a1Lo.x, a1Hi.x, a1Lo.y, a1Hi.y, bv.x, bv.y);
            }
        }
        // ---- epilogue for group g ----
        int Ts = LGG - g;
        unsigned* pool = d_pooled + b * 300 + g * 100;
        #pragma unroll
        for (int tt = 0; tt < 2; ++tt) {
            int tA = t0 + wid * 32 + tt * 16 + (lane >> 2);
            int tB = tA + 8;
            #pragma unroll
            for (int nt = 0; nt < 13; ++nt) {
                float v0 = (tA < Ts) ? acc[tt][nt][0] : -1e30f;
                float v1 = (tA < Ts) ? acc[tt][nt][1] : -1e30f;
                float v2 = (tB < Ts) ? acc[tt][nt][2] : -1e30f;
                float v3 = (tB < Ts) ? acc[tt][nt][3] : -1e30f;
                v0 = fmaxf(v0, v2);
                v1 = fmaxf(v1, v3);
                #pragma unroll
                for (int off = 16; off >= 4; off >>= 1) {
                    v0 = fmaxf(v0, __shfl_xor_sync(0xffffffffu, v0, off));
                    v1 = fmaxf(v1, __shfl_xor_sync(0xffffffffu, v1, off));
                }
                if (lane < 4) {
                    int f0 = nt * 8 + lane * 2;
                    float r0v = fmaxf(v0 + sBias[g][f0], 0.f);
                    float r1v = fmaxf(v1 + sBias[g][f0 + 1], 0.f);
                    if (f0 < 100)     atomicMax(&pool[f0],     __float_as_uint(r0v));
                    if (f0 + 1 < 100) atomicMax(&pool[f0 + 1], __float_as_uint(r1v));
                }
            }
        }
    }
}

// ---------------- K6: global_units ----------------
__global__ void k_global(const float* __restrict__ mf_w, const float* __restrict__ mf_b) {
    __shared__ float ps[300];
    int b = blockIdx.x, tid = threadIdx.x;
    for (int u = tid; u < 300; u += 128) ps[u] = __uint_as_float(d_pooled[b * 300 + u]);
    __syncthreads();
    if (tid >= 100) return;
    float acc = mf_b[tid];
    const float* wr = mf_w + tid * 300;
    #pragma unroll 4
    for (int i = 0; i < 300; ++i) acc += ps[i] * wr[i];
    d_combine[b * 200 + 100 + tid] = acc;
}

// ---------------- K7: hidden ----------------
__global__ void k_fin(const float* __restrict__ fin_w, const float* __restrict__ fin_b) {
    __shared__ float cs[200];
    int b = blockIdx.x, tid = threadIdx.x;
    if (tid < 200) cs[tid] = d_combine[b * 200 + tid];
    __syncthreads();
    if (tid >= 400) return;
    float acc = fin_b[tid];
    const float* wr = fin_w + tid * 200;
    #pragma unroll 4
    for (int d = 0; d < 200; ++d) acc += cs[d] * wr[d];
    d_hidden[b * 400 + tid] = fmaxf(acc, 0.f);
}

// ---------------- K8: out = hidden @ fin2_w.T + b ----------------
__global__ void __launch_bounds__(512) k_out(const float* __restrict__ fw,
                                             const float* __restrict__ fb,
                                             float* __restrict__ out) {
    __shared__ float hs[64 * 100];
    int c0 = blockIdx.x * 128;
    int b0 = blockIdx.y * 64;
    int tid = threadIdx.x;
    int ci = tid & 127, bg = tid >> 7;
    int c = c0 + ci;
    bool cvalid = (c < NCLS);

    unsigned long long acc[16];
    #pragma unroll
    for (int i = 0; i < 16; ++i) acc[i] = 0ull;

    for (int p = 0; p < 4; ++p) {
        __syncthreads();
        for (int u = tid; u < 64 * 100; u += 512)
            hs[u] = d_hidden[(b0 + u / 100) * 400 + p * 100 + (u % 100)];
        __syncthreads();
        if (cvalid) {
            const float* wr = fw + (long)c * 400 + p * 100;
            const float* hb = hs + bg * 16 * 100;
            for (int h = 0; h < 100; h += 2) {
                unsigned long long wv = *reinterpret_cast<const unsigned long long*>(wr + h);
                #pragma unroll
                for (int i = 0; i < 16; ++i) {
                    unsigned long long hv =
                        *reinterpret_cast<const unsigned long long*>(hb + i * 100 + h);
                    acc[i] = ffma2(wv, hv, acc[i]);
                }
            }
        }
    }
    if (cvalid) {
        float bias = fb[c];
        #pragma unroll
        for (int i = 0; i < 16; ++i)
            out[(long)(b0 + bg * 16 + i) * NCLS + c] = acc2_sum(acc[i]) + bias;
    }
}

// ---------------- launcher ----------------
extern "C" void kernel_launch(void* const* d_in, const int* in_sizes, int n_in,
                              void* d_out, int out_size) {
    const int*   ltext  = (const int*)d_in[0];
    const int*   gtext  = (const int*)d_in[1];
    const float* emb    = (const float*)d_in[2];
    const float* att_w  = (const float*)d_in[3];
    const float* att_b  = (const float*)d_in[4];
    const float* att2_w = (const float*)d_in[5];
    const float* att2_b = (const float*)d_in[6];
    const float* c1w    = (const float*)d_in[7];
    const float* c1b    = (const float*)d_in[8];
    const float* c2w    = (const float*)d_in[9];
    const float* c2b    = (const float*)d_in[10];
    const float* c3w    = (const float*)d_in[11];
    const float* c3b    = (const float*)d_in[12];
    const float* mfw    = (const float*)d_in[13];
    const float* mfb    = (const float*)d_in[14];
    const float* finw   = (const float*)d_in[15];
    const float* finb   = (const float*)d_in[16];
    const float* f2w    = (const float*)d_in[17];
    const float* f2b    = (const float*)d_in[18];
    float* out = (float*)d_out;

    k_zero<<<300, 256>>>();
    k_token<<<(BB * LLEN + 3) / 4, 128>>>(ltext, emb, att_w, att_b);
    k_cmp<<<PP, 256>>>();
    k_conv_mma<<<dim3(5, BB), 96>>>(gtext, emb, c1w, c1b, c2w, c2b, c3w, c3b);
    k_scan<<<BB, 128>>>(ltext, emb);
    k_local<<<BB, 128>>>(att2_w, att2_b);
    k_global<<<BB, 128>>>(mfw, mfb);
    k_fin<<<BB, 512>>>(finw, finb);
    k_out<<<dim3(24, 4), 512>>>(f2w, f2b, out);
}

// round 11
// speedup vs baseline: 1.3356x; 1.3356x over previous
#include <cuda_runtime.h>
#include <math.h>
#include <stdint.h>

#define BB   256
#define DM   100
#define LLEN 415
#define LGG  411
#define PP   411
#define NF   100
#define NCLS 2987

// ---------------- scratch (device globals; no allocation) ----------------
__device__ float    d_Asum[BB * LLEN];
__device__ float    d_Tsum[BB * LLEN];
__device__ float    d_cmp[PP];
__device__ float    d_tw[BB * DM];
__device__ unsigned d_pooled[BB * 300];
__device__ float    d_combine[BB * 200];
__device__ float    d_hidden[BB * 400];
__device__ __align__(16) uint32_t d_wbf[42 * 832];   // pre-converted W slices

// packed f32x2 FMA
__device__ __forceinline__ unsigned long long ffma2(unsigned long long a,
                                                    unsigned long long b,
                                                    unsigned long long c) {
    unsigned long long d;
    asm("fma.rn.f32x2 %0, %1, %2, %3;" : "=l"(d) : "l"(a), "l"(b), "l"(c));
    return d;
}
__device__ __forceinline__ float acc2_sum(unsigned long long a) {
    return __uint_as_float((unsigned)(a & 0xffffffffull)) +
           __uint_as_float((unsigned)(a >> 32));
}
__device__ __forceinline__ uint32_t pack_bf16(float lo, float hi) {
    uint32_t r;
    asm("cvt.rn.bf16x2.f32 %0, %1, %2;" : "=r"(r) : "f"(hi), "f"(lo));
    return r;
}
__device__ __forceinline__ void mma16n8k16(float* c, uint32_t a0, uint32_t a1,
                                           uint32_t a2, uint32_t a3,
                                           uint32_t b0, uint32_t b1) {
    asm volatile(
        "mma.sync.aligned.m16n8k16.row.col.f32.bf16.bf16.f32 "
        "{%0,%1,%2,%3}, {%4,%5,%6,%7}, {%8,%9}, {%0,%1,%2,%3};"
        : "+f"(c[0]), "+f"(c[1]), "+f"(c[2]), "+f"(c[3])
        : "r"(a0), "r"(a1), "r"(a2), "r"(a3), "r"(b0), "r"(b1));
}
__device__ __forceinline__ int dec_g(int q) {
    return (q < 7) ? 0 : (q < 21) ? 1 : 2;
}
__device__ __forceinline__ uint32_t smem_u32p(const void* p) {
    return (uint32_t)__cvta_generic_to_shared(p);
}
__device__ __forceinline__ void cp_async16(uint32_t saddr, const void* g) {
    asm volatile("cp.async.cg.shared.global [%0], [%1], 16;"
                 :: "r"(saddr), "l"(g) : "memory");
}
__device__ __forceinline__ void cp_commit() {
    asm volatile("cp.async.commit_group;" ::: "memory");
}
template <int N>
__device__ __forceinline__ void cp_wait() {
    asm volatile("cp.async.wait_group %0;" :: "n"(N) : "memory");
}

// ---------------- K0: pre-convert W to bf16x2 slice layout ----------------
__global__ void k_wprep(const float* __restrict__ w1, const float* __restrict__ w2,
                        const float* __restrict__ w3) {
    int idx = blockIdx.x * blockDim.x + threadIdx.x;
    if (idx >= 42 * 832) return;
    int q = idx / 832, r = idx - q * 832;
    int g = dec_g(q);
    int base = (g == 0) ? 0 : (g == 1) ? 7 : 21;
    int ii = q - base;
    int sn = ii / 7, ksn = ii - sn * 7;
    int Kg = (g + 1) * 100;
    const float* w = (g == 0) ? w1 : (g == 1) ? w2 : w3;
    int nt = r >> 6, rem = r & 63, ni = rem >> 3, p = rem & 7;
    int qq = (p & 1) ? (p >> 1) + 4 : (p >> 1);
    int k0 = ksn * 16 + 2 * qq;
    int f = nt * 8 + ni;
    float v0 = (f < 100 && k0 < 100) ? w[f * Kg + sn * 100 + k0] : 0.f;
    float v1 = (f < 100 && k0 + 1 < 100) ? w[f * Kg + sn * 100 + k0 + 1] : 0.f;
    d_wbf[idx] = pack_bf16(v0, v1);
}

// ---------------- K1: per-token Asum + row-sum ----------------
__global__ void k_token(const int* __restrict__ ltext, const float* __restrict__ emb,
                        const float* __restrict__ att_w, const float* __restrict__ att_b) {
    int warp = (blockIdx.x * blockDim.x + threadIdx.x) >> 5;
    int lane = threadIdx.x & 31;
    if (warp >= BB * LLEN) return;
    int tok = ltext[warp];
    const float* er = emb + (long)tok * DM;
    float s[5] = {0.f, 0.f, 0.f, 0.f, 0.f};
    float ts = 0.f;
    for (int d = lane; d < DM; d += 32) {
        float e = er[d];
        ts += e;
        s[0] += e * att_w[0 * DM + d];
        s[1] += e * att_w[1 * DM + d];
        s[2] += e * att_w[2 * DM + d];
        s[3] += e * att_w[3 * DM + d];
        s[4] += e * att_w[4 * DM + d];
    }
    #pragma unroll
    for (int o = 16; o > 0; o >>= 1) {
        #pragma unroll
        for (int w = 0; w < 5; ++w) s[w] += __shfl_down_sync(0xffffffffu, s[w], o);
        ts += __shfl_down_sync(0xffffffffu, ts, o);
    }
    if (lane == 0) {
        float a = 0.f;
        #pragma unroll
        for (int w = 0; w < 5; ++w) a += tanhf(s[w] + att_b[w]);
        d_Asum[warp] = a;
        d_Tsum[warp] = ts;
    }
}

// ---------------- K2: comparison[p] ----------------
__global__ void k_cmp() {
    __shared__ float smn[256], smx[256];
    int p = blockIdx.x;
    int b = threadIdx.x;
    const float* a = d_Asum + b * LLEN + p;
    float mn = a[0], mx = a[0];
    #pragma unroll
    for (int w = 1; w < 5; ++w) { float v = a[w]; mn = fminf(mn, v); mx = fmaxf(mx, v); }
    smn[b] = mn; smx[b] = mx;
    __syncthreads();
    for (int sft = 128; sft > 0; sft >>= 1) {
        if (b < sft) {
            smn[b] = fminf(smn[b], smn[b + sft]);
            smx[b] = fmaxf(smx[b], smx[b + sft]);
        }
        __syncthreads();
    }
    if (b == 0) d_cmp[p] = 0.8f * smn[0] + 0.8f * smx[0];
}

// ---------------- K3: judge + scan (fp32-exact truncation) ----------------
#define SCAN_KEEP 64
#define SCAN_START (PP - SCAN_KEEP)
__global__ void k_scan(const int* __restrict__ ltext, const float* __restrict__ emb) {
    __shared__ int   toks[SCAN_KEEP];
    __shared__ float jflag[SCAN_KEEP];
    int b = blockIdx.x, tid = threadIdx.x;
    if (tid < SCAN_KEEP) {
        int p = SCAN_START + tid;
        toks[tid]  = ltext[b * LLEN + p + 2];
        jflag[tid] = (d_Tsum[b * LLEN + p + 2] > d_cmp[p]) ? 1.f : 0.f;
    }
    __syncthreads();
    if (tid >= DM) return;
    const float r = 1.0f / 411.0f;
    float tw = 0.f;
    #pragma unroll 8
    for (int i = 0; i < SCAN_KEEP; ++i) {
        float e = emb[(long)toks[i] * DM + tid] * jflag[i];
        tw = (tw + e) * r;
    }
    d_tw[b * DM + tid] = tw;
}

// ---------------- K4: local_units ----------------
__global__ void k_local(const float* __restrict__ att2_w, const float* __restrict__ att2_b) {
    __shared__ float twr[DM];
    int b = blockIdx.x, tid = threadIdx.x;
    if (tid < DM) twr[tid] = d_tw[b * DM + tid];
    __syncthreads();
    if (tid >= DM) return;
    float acc = att2_b[tid];
    const float* wr = att2_w + tid * DM;
    #pragma unroll 4
    for (int d = 0; d < DM; ++d) acc += twr[d] * wr[d];
    d_combine[b * 200 + tid] = acc;
}

// ---------------- zero pooled ----------------
__global__ void k_zero() {
    int i = blockIdx.x * blockDim.x + threadIdx.x;
    if (i < BB * 300) d_pooled[i] = 0u;
}

// ---------------- K5: conv via mma.sync bf16, cp.async B pipeline ----------
// R9 shape (192 thr = 6 warps x m16, 96-t tile, 13 n-tiles) + 4-deep cp.async
// ring for B slices from pre-converted d_wbf. One barrier per slice.
#define EP2 60
#define NBUF 4
__global__ void __launch_bounds__(192, 4) k_conv_mma(
    const int* __restrict__ gtext, const float* __restrict__ emb,
    const float* __restrict__ cb1, const float* __restrict__ cb2,
    const float* __restrict__ cb3) {
    __shared__ __align__(16) uint32_t EgS[98 * EP2];    // 23520 B
    __shared__ __align__(16) uint32_t Bs[NBUF][832];    // 13312 B
    __shared__ float sBias[3][104];
    int tid = threadIdx.x, lane = tid & 31, wid = tid >> 5;
    int t0 = blockIdx.x * 96, b = blockIdx.y;

    const float* cbs[3] = {cb1, cb2, cb3};
    for (int u = tid; u < 312; u += 192) {
        int g = u / 104, f = u - g * 104;
        sBias[g][f] = (f < 100) ? cbs[g][f] : 0.f;
    }
    // E tile rows t0..t0+97 as bf16x2, pair-interleaved within 8-pair blocks
    for (int r = wid; r < 98; r += 6) {
        int gt = t0 + r;
        const float* er = (gt < LGG) ? emb + (long)gtext[b * LGG + gt] * DM : 0;
        for (int qq = lane; qq < 56; qq += 32) {
            int c0 = 2 * qq;
            float v0 = (er && c0 < 100) ? er[c0] : 0.f;
            float v1 = (er && c0 + 1 < 100) ? er[c0 + 1] : 0.f;
            int bq = qq & 7;
            int p = (bq < 4) ? 2 * bq : 2 * (bq - 4) + 1;
            EgS[r * EP2 + (qq & ~7) + p] = pack_bf16(v0, v1);
        }
    }

    // cp.async pipeline: issue slice j into Bs[j % NBUF] (208 x 16B chunks)
    uint32_t bs_base[NBUF];
    #pragma unroll
    for (int j = 0; j < NBUF; ++j) bs_base[j] = smem_u32p(&Bs[j][0]);
    int chunk = tid;   // 0..191; chunks 192..207 by threads 0..15 second pass
    #pragma unroll
    for (int j = 0; j < 3; ++j) {                       // prologue: slices 0..2
        if (chunk < 208) cp_async16(bs_base[j] + chunk * 16, &d_wbf[j * 832 + chunk * 4]);
        if (tid < 16)    cp_async16(bs_base[j] + (192 + tid) * 16,
                                    &d_wbf[j * 832 + (192 + tid) * 4]);
        cp_commit();
    }

    int q = 0;
    for (int g = 0; g < 3; ++g) {
        float acc[13][4];
        #pragma unroll
        for (int nt = 0; nt < 13; ++nt)
            #pragma unroll
            for (int j = 0; j < 4; ++j) acc[nt][j] = 0.f;
        int ns = (g + 1) * 7;
        for (int i = 0; i < ns; ++i, ++q) {
            cp_wait<2>();                // slice q landed
            __syncthreads();             // visible to all; prev buf reusable
            {                            // issue slice q+3 (or empty commit)
                int jn = q + 3;
                if (jn < 42) {
                    uint32_t sb = bs_base[jn & 3];
                    const uint32_t* gp = &d_wbf[jn * 832];
                    cp_async16(sb + chunk * 16, gp + chunk * 4);
                    if (tid < 16) cp_async16(sb + (192 + tid) * 16, gp + (192 + tid) * 4);
                }
                cp_commit();
            }
            const uint32_t* Bcur = &Bs[q & 3][0];
            int s = i / 7, ks = i - s * 7;
            int r0 = wid * 16 + (lane >> 2) + s;
            int ab = ks * 8 + 2 * (lane & 3);
            uint2 aLo = *reinterpret_cast<const uint2*>(&EgS[r0 * EP2 + ab]);
            uint2 aHi = *reinterpret_cast<const uint2*>(&EgS[(r0 + 8) * EP2 + ab]);
            const uint32_t* bp = Bcur + (lane >> 2) * 8 + 2 * (lane & 3);
            #pragma unroll
            for (int nt = 0; nt < 13; ++nt) {
                uint2 bv = *reinterpret_cast<const uint2*>(bp + nt * 64);
                mma16n8k16(acc[nt], aLo.x, aHi.x, aLo.y, aHi.y, bv.x, bv.y);
            }
        }
        // ---- epilogue for group g ----
        int Ts = LGG - g;
        int tA = t0 + wid * 16 + (lane >> 2);
        int tB = tA + 8;
        unsigned* pool = d_pooled + b * 300 + g * 100;
        #pragma unroll
        for (int nt = 0; nt < 13; ++nt) {
            float v0 = (tA < Ts) ? acc[nt][0] : -1e30f;
            float v1 = (tA < Ts) ? acc[nt][1] : -1e30f;
            float v2 = (tB < Ts) ? acc[nt][2] : -1e30f;
            float v3 = (tB < Ts) ? acc[nt][3] : -1e30f;
            v0 = fmaxf(v0, v2);
            v1 = fmaxf(v1, v3);
            #pragma unroll
            for (int off = 16; off >= 4; off >>= 1) {
                v0 = fmaxf(v0, __shfl_xor_sync(0xffffffffu, v0, off));
                v1 = fmaxf(v1, __shfl_xor_sync(0xffffffffu, v1, off));
            }
            if (lane < 4) {
                int f0 = nt * 8 + lane * 2;
                float r0v = fmaxf(v0 + sBias[g][f0], 0.f);
                float r1v = fmaxf(v1 + sBias[g][f0 + 1], 0.f);
                if (f0 < 100)     atomicMax(&pool[f0],     __float_as_uint(r0v));
                if (f0 + 1 < 100) atomicMax(&pool[f0 + 1], __float_as_uint(r1v));
            }
        }
    }
}

// ---------------- K6: global_units ----------------
__global__ void k_global(const float* __restrict__ mf_w, const float* __restrict__ mf_b) {
    __shared__ float ps[300];
    int b = blockIdx.x, tid = threadIdx.x;
    for (int u = tid; u < 300; u += 128) ps[u] = __uint_as_float(d_pooled[b * 300 + u]);
    __syncthreads();
    if (tid >= 100) return;
    float acc = mf_b[tid];
    const float* wr = mf_w + tid * 300;
    #pragma unroll 4
    for (int i = 0; i < 300; ++i) acc += ps[i] * wr[i];
    d_combine[b * 200 + 100 + tid] = acc;
}

// ---------------- K7: hidden ----------------
__global__ void k_fin(const float* __restrict__ fin_w, const float* __restrict__ fin_b) {
    __shared__ float cs[200];
    int b = blockIdx.x, tid = threadIdx.x;
    if (tid < 200) cs[tid] = d_combine[b * 200 + tid];
    __syncthreads();
    if (tid >= 400) return;
    float acc = fin_b[tid];
    const float* wr = fin_w + tid * 200;
    #pragma unroll 4
    for (int d = 0; d < 200; ++d) acc += cs[d] * wr[d];
    d_hidden[b * 400 + tid] = fmaxf(acc, 0.f);
}

// ---------------- K8: out = hidden @ fin2_w.T + b ----------------
__global__ void __launch_bounds__(512) k_out(const float* __restrict__ fw,
                                             const float* __restrict__ fb,
                                             float* __restrict__ out) {
    __shared__ float hs[64 * 100];
    int c0 = blockIdx.x * 128;
    int b0 = blockIdx.y * 64;
    int tid = threadIdx.x;
    int ci = tid & 127, bg = tid >> 7;
    int c = c0 + ci;
    bool cvalid = (c < NCLS);

    unsigned long long acc[16];
    #pragma unroll
    for (int i = 0; i < 16; ++i) acc[i] = 0ull;

    for (int p = 0; p < 4; ++p) {
        __syncthreads();
        for (int u = tid; u < 64 * 100; u += 512)
            hs[u] = d_hidden[(b0 + u / 100) * 400 + p * 100 + (u % 100)];
        __syncthreads();
        if (cvalid) {
            const float* wr = fw + (long)c * 400 + p * 100;
            const float* hb = hs + bg * 16 * 100;
            for (int h = 0; h < 100; h += 2) {
                unsigned long long wv = *reinterpret_cast<const unsigned long long*>(wr + h);
                #pragma unroll
                for (int i = 0; i < 16; ++i) {
                    unsigned long long hv =
                        *reinterpret_cast<const unsigned long long*>(hb + i * 100 + h);
                    acc[i] = ffma2(wv, hv, acc[i]);
                }
            }
        }
    }
    if (cvalid) {
        float bias = fb[c];
        #pragma unroll
        for (int i = 0; i < 16; ++i)
            out[(long)(b0 + bg * 16 + i) * NCLS + c] = acc2_sum(acc[i]) + bias;
    }
}

// ---------------- launcher ----------------
extern "C" void kernel_launch(void* const* d_in, const int* in_sizes, int n_in,
                              void* d_out, int out_size) {
    const int*   ltext  = (const int*)d_in[0];
    const int*   gtext  = (const int*)d_in[1];
    const float* emb    = (const float*)d_in[2];
    const float* att_w  = (const float*)d_in[3];
    const float* att_b  = (const float*)d_in[4];
    const float* att2_w = (const float*)d_in[5];
    const float* att2_b = (const float*)d_in[6];
    const float* c1w    = (const float*)d_in[7];
    const float* c1b    = (const float*)d_in[8];
    const float* c2w    = (const float*)d_in[9];
    const float* c2b    = (const float*)d_in[10];
    const float* c3w    = (const float*)d_in[11];
    const float* c3b    = (const float*)d_in[12];
    const float* mfw    = (const float*)d_in[13];
    const float* mfb    = (const float*)d_in[14];
    const float* finw   = (const float*)d_in[15];
    const float* finb   = (const float*)d_in[16];
    const float* f2w    = (const float*)d_in[17];
    const float* f2b    = (const float*)d_in[18];
    float* out = (float*)d_out;

    k_zero<<<300, 256>>>();
    k_wprep<<<(42 * 832 + 255) / 256, 256>>>(c1w, c2w, c3w);
    k_token<<<(BB * LLEN + 3) / 4, 128>>>(ltext, emb, att_w, att_b);
    k_conv_mma<<<dim3(5, BB), 192>>>(gtext, emb, c1b, c2b, c3b);
    k_cmp<<<PP, 256>>>();
    k_scan<<<BB, 128>>>(ltext, emb);
    k_local<<<BB, 128>>>(att2_w, att2_b);
    k_global<<<BB, 128>>>(mfw, mfb);
    k_fin<<<BB, 512>>>(finw, finb);
    k_out<<<dim3(24, 4), 512>>>(f2w, f2b, out);
}

// round 12
// speedup vs baseline: 1.4040x; 1.0513x over previous
#include <cuda_runtime.h>
#include <math.h>
#include <stdint.h>

#define BB   256
#define DM   100
#define LLEN 415
#define LGG  411
#define PP   411
#define NF   100
#define NCLS 2987

// ---------------- scratch (device globals; no allocation) ----------------
__device__ float    d_Asum[BB * LLEN];
__device__ float    d_Tsum[BB * LLEN];
__device__ float    d_cmp[PP];
__device__ float    d_tw[BB * DM];
__device__ unsigned d_pooled[BB * 300];
__device__ float    d_combine[BB * 200];
__device__ float    d_hidden[BB * 400];
__device__ __align__(16) uint32_t d_wbf[42 * 832];   // pre-converted W slices

// packed f32x2 FMA
__device__ __forceinline__ unsigned long long ffma2(unsigned long long a,
                                                    unsigned long long b,
                                                    unsigned long long c) {
    unsigned long long d;
    asm("fma.rn.f32x2 %0, %1, %2, %3;" : "=l"(d) : "l"(a), "l"(b), "l"(c));
    return d;
}
__device__ __forceinline__ float acc2_sum(unsigned long long a) {
    return __uint_as_float((unsigned)(a & 0xffffffffull)) +
           __uint_as_float((unsigned)(a >> 32));
}
__device__ __forceinline__ uint32_t pack_bf16(float lo, float hi) {
    uint32_t r;
    asm("cvt.rn.bf16x2.f32 %0, %1, %2;" : "=r"(r) : "f"(hi), "f"(lo));
    return r;
}
__device__ __forceinline__ void mma16n8k16(float* c, uint32_t a0, uint32_t a1,
                                           uint32_t a2, uint32_t a3,
                                           uint32_t b0, uint32_t b1) {
    asm volatile(
        "mma.sync.aligned.m16n8k16.row.col.f32.bf16.bf16.f32 "
        "{%0,%1,%2,%3}, {%4,%5,%6,%7}, {%8,%9}, {%0,%1,%2,%3};"
        : "+f"(c[0]), "+f"(c[1]), "+f"(c[2]), "+f"(c[3])
        : "r"(a0), "r"(a1), "r"(a2), "r"(a3), "r"(b0), "r"(b1));
}
__device__ __forceinline__ int dec_g(int q) {
    return (q < 7) ? 0 : (q < 21) ? 1 : 2;
}
__device__ __forceinline__ uint32_t smem_u32p(const void* p) {
    return (uint32_t)__cvta_generic_to_shared(p);
}
__device__ __forceinline__ void cp_async16(uint32_t saddr, const void* g) {
    asm volatile("cp.async.cg.shared.global [%0], [%1], 16;"
                 :: "r"(saddr), "l"(g) : "memory");
}
__device__ __forceinline__ void cp_commit() {
    asm volatile("cp.async.commit_group;" ::: "memory");
}
template <int N>
__device__ __forceinline__ void cp_wait() {
    asm volatile("cp.async.wait_group %0;" :: "n"(N) : "memory");
}

#define SCAN_KEEP 64
#define SCAN_START (PP - SCAN_KEEP)   // 347
#define TOKP (SCAN_KEEP + 4)          // 68 positions: 347..414

// ---------------- K0: pre-convert W to bf16x2 slice layout ----------------
__global__ void k_wprep(const float* __restrict__ w1, const float* __restrict__ w2,
                        const float* __restrict__ w3) {
    int idx = blockIdx.x * blockDim.x + threadIdx.x;
    if (idx >= 42 * 832) return;
    int q = idx / 832, r = idx - q * 832;
    int g = dec_g(q);
    int base = (g == 0) ? 0 : (g == 1) ? 7 : 21;
    int ii = q - base;
    int sn = ii / 7, ksn = ii - sn * 7;
    int Kg = (g + 1) * 100;
    const float* w = (g == 0) ? w1 : (g == 1) ? w2 : w3;
    int nt = r >> 6, rem = r & 63, ni = rem >> 3, p = rem & 7;
    int qq = (p & 1) ? (p >> 1) + 4 : (p >> 1);
    int k0 = ksn * 16 + 2 * qq;
    int f = nt * 8 + ni;
    float v0 = (f < 100 && k0 < 100) ? w[f * Kg + sn * 100 + k0] : 0.f;
    float v1 = (f < 100 && k0 + 1 < 100) ? w[f * Kg + sn * 100 + k0 + 1] : 0.f;
    d_wbf[idx] = pack_bf16(v0, v1);
}

// ---------------- K1: per-token Asum + row-sum (positions 347..414 only) ----
__global__ void k_token(const int* __restrict__ ltext, const float* __restrict__ emb,
                        const float* __restrict__ att_w, const float* __restrict__ att_b) {
    int warp = (blockIdx.x * blockDim.x + threadIdx.x) >> 5;
    int lane = threadIdx.x & 31;
    if (warp >= BB * TOKP) return;
    int b = warp / TOKP;
    int pos = SCAN_START + (warp - b * TOKP);
    int tok = ltext[b * LLEN + pos];
    const float* er = emb + (long)tok * DM;
    float s[5] = {0.f, 0.f, 0.f, 0.f, 0.f};
    float ts = 0.f;
    for (int d = lane; d < DM; d += 32) {
        float e = er[d];
        ts += e;
        s[0] += e * att_w[0 * DM + d];
        s[1] += e * att_w[1 * DM + d];
        s[2] += e * att_w[2 * DM + d];
        s[3] += e * att_w[3 * DM + d];
        s[4] += e * att_w[4 * DM + d];
    }
    #pragma unroll
    for (int o = 16; o > 0; o >>= 1) {
        #pragma unroll
        for (int w = 0; w < 5; ++w) s[w] += __shfl_down_sync(0xffffffffu, s[w], o);
        ts += __shfl_down_sync(0xffffffffu, ts, o);
    }
    if (lane == 0) {
        float a = 0.f;
        #pragma unroll
        for (int w = 0; w < 5; ++w) a += tanhf(s[w] + att_b[w]);
        d_Asum[b * LLEN + pos] = a;
        d_Tsum[b * LLEN + pos] = ts;
    }
}

// ---------------- K2: comparison[p], p in 347..410 only ----------------
__global__ void k_cmp() {
    __shared__ float smn[256], smx[256];
    int p = SCAN_START + blockIdx.x;
    int b = threadIdx.x;
    const float* a = d_Asum + b * LLEN + p;
    float mn = a[0], mx = a[0];
    #pragma unroll
    for (int w = 1; w < 5; ++w) { float v = a[w]; mn = fminf(mn, v); mx = fmaxf(mx, v); }
    smn[b] = mn; smx[b] = mx;
    __syncthreads();
    for (int sft = 128; sft > 0; sft >>= 1) {
        if (b < sft) {
            smn[b] = fminf(smn[b], smn[b + sft]);
            smx[b] = fmaxf(smx[b], smx[b + sft]);
        }
        __syncthreads();
    }
    if (b == 0) d_cmp[p] = 0.8f * smn[0] + 0.8f * smx[0];
}

// ---------------- K3: judge + scan (fp32-exact truncation) ----------------
__global__ void k_scan(const int* __restrict__ ltext, const float* __restrict__ emb) {
    __shared__ int   toks[SCAN_KEEP];
    __shared__ float jflag[SCAN_KEEP];
    int b = blockIdx.x, tid = threadIdx.x;
    if (tid < SCAN_KEEP) {
        int p = SCAN_START + tid;
        toks[tid]  = ltext[b * LLEN + p + 2];
        jflag[tid] = (d_Tsum[b * LLEN + p + 2] > d_cmp[p]) ? 1.f : 0.f;
    }
    __syncthreads();
    if (tid >= DM) return;
    const float r = 1.0f / 411.0f;
    float tw = 0.f;
    #pragma unroll 8
    for (int i = 0; i < SCAN_KEEP; ++i) {
        float e = emb[(long)toks[i] * DM + tid] * jflag[i];
        tw = (tw + e) * r;
    }
    d_tw[b * DM + tid] = tw;
}

// ---------------- K4: local_units ----------------
__global__ void k_local(const float* __restrict__ att2_w, const float* __restrict__ att2_b) {
    __shared__ float twr[DM];
    int b = blockIdx.x, tid = threadIdx.x;
    if (tid < DM) twr[tid] = d_tw[b * DM + tid];
    __syncthreads();
    if (tid >= DM) return;
    float acc = att2_b[tid];
    const float* wr = att2_w + tid * DM;
    #pragma unroll 4
    for (int d = 0; d < DM; ++d) acc += twr[d] * wr[d];
    d_combine[b * 200 + tid] = acc;
}

// ---------------- zero pooled ----------------
__global__ void k_zero() {
    int i = blockIdx.x * blockDim.x + threadIdx.x;
    if (i < BB * 300) d_pooled[i] = 0u;
}

// ---------------- K5: conv via mma.sync bf16, 3Mx2N warp tiling -----------
// 6 warps = 3 M-groups (32 rows: two m16) x 2 N-groups (7 / 6 n-tiles).
// Per slice per warp: 4 A + <=7 B LDS.64 -> <=14 MMAs. Block LDS ~16 KB/slice
// (vs 23 in R11). EP2=56 -> A-fragment LDS.64 conflict-free. cp.async B ring.
#define EP2 56
#define NBUF 4
__global__ void __launch_bounds__(192, 4) k_conv_mma(
    const int* __restrict__ gtext, const float* __restrict__ emb,
    const float* __restrict__ cb1, const float* __restrict__ cb2,
    const float* __restrict__ cb3) {
    __shared__ __align__(16) uint32_t EgS[98 * EP2];    // 21952 B
    __shared__ __align__(16) uint32_t Bs[NBUF][832];    // 13312 B
    __shared__ float sBias[3][104];
    int tid = threadIdx.x, lane = tid & 31, wid = tid >> 5;
    int mg = wid >> 1, ng = wid & 1;
    int ntbase = ng * 7;
    int ntcnt = ng ? 6 : 7;
    int t0 = blockIdx.x * 96, b = blockIdx.y;

    const float* cbs[3] = {cb1, cb2, cb3};
    for (int u = tid; u < 312; u += 192) {
        int g = u / 104, f = u - g * 104;
        sBias[g][f] = (f < 100) ? cbs[g][f] : 0.f;
    }
    // E tile rows t0..t0+97 as bf16x2, pair-interleaved within 8-pair blocks
    for (int r = wid; r < 98; r += 6) {
        int gt = t0 + r;
        const float* er = (gt < LGG) ? emb + (long)gtext[b * LGG + gt] * DM : 0;
        for (int qq = lane; qq < EP2; qq += 32) {
            int c0 = 2 * qq;
            float v0 = (er && c0 < 100) ? er[c0] : 0.f;
            float v1 = (er && c0 + 1 < 100) ? er[c0 + 1] : 0.f;
            int bq = qq & 7;
            int p = (bq < 4) ? 2 * bq : 2 * (bq - 4) + 1;
            EgS[r * EP2 + (qq & ~7) + p] = pack_bf16(v0, v1);
        }
    }

    // cp.async pipeline: issue slice j into Bs[j % NBUF] (208 x 16B chunks)
    uint32_t bs_base[NBUF];
    #pragma unroll
    for (int j = 0; j < NBUF; ++j) bs_base[j] = smem_u32p(&Bs[j][0]);
    int chunk = tid;
    #pragma unroll
    for (int j = 0; j < 3; ++j) {                       // prologue: slices 0..2
        if (chunk < 208) cp_async16(bs_base[j] + chunk * 16, &d_wbf[j * 832 + chunk * 4]);
        if (tid < 16)    cp_async16(bs_base[j] + (192 + tid) * 16,
                                    &d_wbf[j * 832 + (192 + tid) * 4]);
        cp_commit();
    }

    int q = 0;
    for (int g = 0; g < 3; ++g) {
        float acc[2][7][4];
        #pragma unroll
        for (int tt = 0; tt < 2; ++tt)
            #pragma unroll
            for (int nt = 0; nt < 7; ++nt)
                #pragma unroll
                for (int j = 0; j < 4; ++j) acc[tt][nt][j] = 0.f;
        int ns = (g + 1) * 7;
        for (int i = 0; i < ns; ++i, ++q) {
            cp_wait<2>();
            __syncthreads();
            {                            // issue slice q+3
                int jn = q + 3;
                if (jn < 42) {
                    uint32_t sb = bs_base[jn & 3];
                    const uint32_t* gp = &d_wbf[jn * 832];
                    cp_async16(sb + chunk * 16, gp + chunk * 4);
                    if (tid < 16) cp_async16(sb + (192 + tid) * 16, gp + (192 + tid) * 4);
                }
                cp_commit();
            }
            const uint32_t* Bcur = &Bs[q & 3][0];
            int s = i / 7, ks = i - s * 7;
            int r0 = mg * 32 + (lane >> 2) + s;
            int ab = ks * 8 + 2 * (lane & 3);
            uint2 a0Lo = *reinterpret_cast<const uint2*>(&EgS[r0 * EP2 + ab]);
            uint2 a0Hi = *reinterpret_cast<const uint2*>(&EgS[(r0 + 8) * EP2 + ab]);
            uint2 a1Lo = *reinterpret_cast<const uint2*>(&EgS[(r0 + 16) * EP2 + ab]);
            uint2 a1Hi = *reinterpret_cast<const uint2*>(&EgS[(r0 + 24) * EP2 + ab]);
            const uint32_t* bp = Bcur + ntbase * 64 + (lane >> 2) * 8 + 2 * (lane & 3);
            #pragma unroll
            for (int nt = 0; nt < 7; ++nt) {
                if (nt < ntcnt) {
                    uint2 bv = *reinterpret_cast<const uint2*>(bp + nt * 64);
                    mma16n8k16(acc[0][nt], a0Lo.x, a0Hi.x, a0Lo.y, a0Hi.y, bv.x, bv.y);
                    mma16n8k16(acc[1][nt], a1Lo.x, a1Hi.x, a1Lo.y, a1Hi.y, bv.x, bv.y);
                }
            }
        }
        // ---- epilogue for group g ----
        int Ts = LGG - g;
        unsigned* pool = d_pooled + b * 300 + g * 100;
        #pragma unroll
        for (int tt = 0; tt < 2; ++tt) {
            int tA = t0 + mg * 32 + tt * 16 + (lane >> 2);
            int tB = tA + 8;
            #pragma unroll
            for (int nt = 0; nt < 7; ++nt) {
                if (nt < ntcnt) {
                    float v0 = (tA < Ts) ? acc[tt][nt][0] : -1e30f;
                    float v1 = (tA < Ts) ? acc[tt][nt][1] : -1e30f;
                    float v2 = (tB < Ts) ? acc[tt][nt][2] : -1e30f;
                    float v3 = (tB < Ts) ? acc[tt][nt][3] : -1e30f;
                    v0 = fmaxf(v0, v2);
                    v1 = fmaxf(v1, v3);
                    #pragma unroll
                    for (int off = 16; off >= 4; off >>= 1) {
                        v0 = fmaxf(v0, __shfl_xor_sync(0xffffffffu, v0, off));
                        v1 = fmaxf(v1, __shfl_xor_sync(0xffffffffu, v1, off));
                    }
                    if (lane < 4) {
                        int f0 = (ntbase + nt) * 8 + lane * 2;
                        float r0v = fmaxf(v0 + sBias[g][f0], 0.f);
                        float r1v = fmaxf(v1 + sBias[g][f0 + 1], 0.f);
                        if (f0 < 100)     atomicMax(&pool[f0],     __float_as_uint(r0v));
                        if (f0 + 1 < 100) atomicMax(&pool[f0 + 1], __float_as_uint(r1v));
                    }
                }
            }
        }
    }
}

// ---------------- K6: global_units ----------------
__global__ void k_global(const float* __restrict__ mf_w, const float* __restrict__ mf_b) {
    __shared__ float ps[300];
    int b = blockIdx.x, tid = threadIdx.x;
    for (int u = tid; u < 300; u += 128) ps[u] = __uint_as_float(d_pooled[b * 300 + u]);
    __syncthreads();
    if (tid >= 100) return;
    float acc = mf_b[tid];
    const float* wr = mf_w + tid * 300;
    #pragma unroll 4
    for (int i = 0; i < 300; ++i) acc += ps[i] * wr[i];
    d_combine[b * 200 + 100 + tid] = acc;
}

// ---------------- K7: hidden ----------------
__global__ void k_fin(const float* __restrict__ fin_w, const float* __restrict__ fin_b) {
    __shared__ float cs[200];
    int b = blockIdx.x, tid = threadIdx.x;
    if (tid < 200) cs[tid] = d_combine[b * 200 + tid];
    __syncthreads();
    if (tid >= 400) return;
    float acc = fin_b[tid];
    const float* wr = fin_w + tid * 200;
    #pragma unroll 4
    for (int d = 0; d < 200; ++d) acc += cs[d] * wr[d];
    d_hidden[b * 400 + tid] = fmaxf(acc, 0.f);
}

// ---------------- K8: out = hidden @ fin2_w.T + b ----------------
__global__ void __launch_bounds__(512) k_out(const float* __restrict__ fw,
                                             const float* __restrict__ fb,
                                             float* __restrict__ out) {
    __shared__ float hs[64 * 100];
    int c0 = blockIdx.x * 128;
    int b0 = blockIdx.y * 64;
    int tid = threadIdx.x;
    int ci = tid & 127, bg = tid >> 7;
    int c = c0 + ci;
    bool cvalid = (c < NCLS);

    unsigned long long acc[16];
    #pragma unroll
    for (int i = 0; i < 16; ++i) acc[i] = 0ull;

    for (int p = 0; p < 4; ++p) {
        __syncthreads();
        for (int u = tid; u < 64 * 100; u += 512)
            hs[u] = d_hidden[(b0 + u / 100) * 400 + p * 100 + (u % 100)];
        __syncthreads();
        if (cvalid) {
            const float* wr = fw + (long)c * 400 + p * 100;
            const float* hb = hs + bg * 16 * 100;
            for (int h = 0; h < 100; h += 2) {
                unsigned long long wv = *reinterpret_cast<const unsigned long long*>(wr + h);
                #pragma unroll
                for (int i = 0; i < 16; ++i) {
                    unsigned long long hv =
                        *reinterpret_cast<const unsigned long long*>(hb + i * 100 + h);
                    acc[i] = ffma2(wv, hv, acc[i]);
                }
            }
        }
    }
    if (cvalid) {
        float bias = fb[c];
        #pragma unroll
        for (int i = 0; i < 16; ++i)
            out[(long)(b0 + bg * 16 + i) * NCLS + c] = acc2_sum(acc[i]) + bias;
    }
}

// ---------------- launcher ----------------
extern "C" void kernel_launch(void* const* d_in, const int* in_sizes, int n_in,
                              void* d_out, int out_size) {
    const int*   ltext  = (const int*)d_in[0];
    const int*   gtext  = (const int*)d_in[1];
    const float* emb    = (const float*)d_in[2];
    const float* att_w  = (const float*)d_in[3];
    const float* att_b  = (const float*)d_in[4];
    const float* att2_w = (const float*)d_in[5];
    const float* att2_b = (const float*)d_in[6];
    const float* c1w    = (const float*)d_in[7];
    const float* c1b    = (const float*)d_in[8];
    const float* c2w    = (const float*)d_in[9];
    const float* c2b    = (const float*)d_in[10];
    const float* c3w    = (const float*)d_in[11];
    const float* c3b    = (const float*)d_in[12];
    const float* mfw    = (const float*)d_in[13];
    const float* mfb    = (const float*)d_in[14];
    const float* finw   = (const float*)d_in[15];
    const float* finb   = (const float*)d_in[16];
    const float* f2w    = (const float*)d_in[17];
    const float* f2b    = (const float*)d_in[18];
    float* out = (float*)d_out;

    k_zero<<<300, 256>>>();
    k_wprep<<<(42 * 832 + 255) / 256, 256>>>(c1w, c2w, c3w);
    k_token<<<(BB * TOKP + 3) / 4, 128>>>(ltext, emb, att_w, att_b);
    k_conv_mma<<<dim3(5, BB), 192>>>(gtext, emb, c1b, c2b, c3b);
    k_cmp<<<SCAN_KEEP, 256>>>();
    k_scan<<<BB, 128>>>(ltext, emb);
    k_local<<<BB, 128>>>(att2_w, att2_b);
    k_global<<<BB, 128>>>(mfw, mfb);
    k_fin<<<BB, 512>>>(finw, finb);
    k_out<<<dim3(24, 4), 512>>>(f2w, f2b, out);
}

// round 13
// speedup vs baseline: 1.5102x; 1.0756x over previous
#include <cuda_runtime.h>
#include <math.h>
#include <stdint.h>

#define BB   256
#define DM   100
#define LLEN 415
#define LGG  411
#define PP   411
#define NF   100
#define NCLS 2987

// ---------------- scratch (device globals; no allocation) ----------------
__device__ float    d_Asum[BB * LLEN];
__device__ float    d_Tsum[BB * LLEN];
__device__ float    d_cmp[PP];
__device__ unsigned d_pooled[BB * 300];
__device__ float    d_hidden[BB * 400];
__device__ __align__(16) uint32_t d_wbf[42 * 832];   // pre-converted W slices

// packed f32x2 FMA
__device__ __forceinline__ unsigned long long ffma2(unsigned long long a,
                                                    unsigned long long b,
                                                    unsigned long long c) {
    unsigned long long d;
    asm("fma.rn.f32x2 %0, %1, %2, %3;" : "=l"(d) : "l"(a), "l"(b), "l"(c));
    return d;
}
__device__ __forceinline__ float acc2_sum(unsigned long long a) {
    return __uint_as_float((unsigned)(a & 0xffffffffull)) +
           __uint_as_float((unsigned)(a >> 32));
}
__device__ __forceinline__ uint32_t pack_bf16(float lo, float hi) {
    uint32_t r;
    asm("cvt.rn.bf16x2.f32 %0, %1, %2;" : "=r"(r) : "f"(hi), "f"(lo));
    return r;
}
__device__ __forceinline__ void mma16n8k16(float* c, uint32_t a0, uint32_t a1,
                                           uint32_t a2, uint32_t a3,
                                           uint32_t b0, uint32_t b1) {
    asm volatile(
        "mma.sync.aligned.m16n8k16.row.col.f32.bf16.bf16.f32 "
        "{%0,%1,%2,%3}, {%4,%5,%6,%7}, {%8,%9}, {%0,%1,%2,%3};"
        : "+f"(c[0]), "+f"(c[1]), "+f"(c[2]), "+f"(c[3])
        : "r"(a0), "r"(a1), "r"(a2), "r"(a3), "r"(b0), "r"(b1));
}
__device__ __forceinline__ int dec_g(int q) {
    return (q < 7) ? 0 : (q < 21) ? 1 : 2;
}
__device__ __forceinline__ uint32_t smem_u32p(const void* p) {
    return (uint32_t)__cvta_generic_to_shared(p);
}
__device__ __forceinline__ void cp_async16(uint32_t saddr, const void* g) {
    asm volatile("cp.async.cg.shared.global [%0], [%1], 16;"
                 :: "r"(saddr), "l"(g) : "memory");
}
__device__ __forceinline__ void cp_commit() {
    asm volatile("cp.async.commit_group;" ::: "memory");
}
template <int N>
__device__ __forceinline__ void cp_wait() {
    asm volatile("cp.async.wait_group %0;" :: "n"(N) : "memory");
}

#define SCAN_KEEP 64
#define SCAN_START (PP - SCAN_KEEP)   // 347
#define TOKP (SCAN_KEEP + 4)          // 68 positions: 347..414

// ---------------- K0: pre-convert W to bf16x2 slice layout ----------------
__global__ void k_wprep(const float* __restrict__ w1, const float* __restrict__ w2,
                        const float* __restrict__ w3) {
    int idx = blockIdx.x * blockDim.x + threadIdx.x;
    if (idx >= 42 * 832) return;
    int q = idx / 832, r = idx - q * 832;
    int g = dec_g(q);
    int base = (g == 0) ? 0 : (g == 1) ? 7 : 21;
    int ii = q - base;
    int sn = ii / 7, ksn = ii - sn * 7;
    int Kg = (g + 1) * 100;
    const float* w = (g == 0) ? w1 : (g == 1) ? w2 : w3;
    int nt = r >> 6, rem = r & 63, ni = rem >> 3, p = rem & 7;
    int qq = (p & 1) ? (p >> 1) + 4 : (p >> 1);
    int k0 = ksn * 16 + 2 * qq;
    int f = nt * 8 + ni;
    float v0 = (f < 100 && k0 < 100) ? w[f * Kg + sn * 100 + k0] : 0.f;
    float v1 = (f < 100 && k0 + 1 < 100) ? w[f * Kg + sn * 100 + k0 + 1] : 0.f;
    d_wbf[idx] = pack_bf16(v0, v1);
}

// ---------------- K1: per-token Asum + row-sum (positions 347..414 only) ----
__global__ void k_token(const int* __restrict__ ltext, const float* __restrict__ emb,
                        const float* __restrict__ att_w, const float* __restrict__ att_b) {
    int warp = (blockIdx.x * blockDim.x + threadIdx.x) >> 5;
    int lane = threadIdx.x & 31;
    if (warp >= BB * TOKP) return;
    int b = warp / TOKP;
    int pos = SCAN_START + (warp - b * TOKP);
    int tok = ltext[b * LLEN + pos];
    const float* er = emb + (long)tok * DM;
    float s[5] = {0.f, 0.f, 0.f, 0.f, 0.f};
    float ts = 0.f;
    for (int d = lane; d < DM; d += 32) {
        float e = er[d];
        ts += e;
        s[0] += e * att_w[0 * DM + d];
        s[1] += e * att_w[1 * DM + d];
        s[2] += e * att_w[2 * DM + d];
        s[3] += e * att_w[3 * DM + d];
        s[4] += e * att_w[4 * DM + d];
    }
    #pragma unroll
    for (int o = 16; o > 0; o >>= 1) {
        #pragma unroll
        for (int w = 0; w < 5; ++w) s[w] += __shfl_down_sync(0xffffffffu, s[w], o);
        ts += __shfl_down_sync(0xffffffffu, ts, o);
    }
    if (lane == 0) {
        float a = 0.f;
        #pragma unroll
        for (int w = 0; w < 5; ++w) a += tanhf(s[w] + att_b[w]);
        d_Asum[b * LLEN + pos] = a;
        d_Tsum[b * LLEN + pos] = ts;
    }
}

// ---------------- K2: comparison[p], p in 347..410 only ----------------
__global__ void k_cmp() {
    __shared__ float smn[256], smx[256];
    int p = SCAN_START + blockIdx.x;
    int b = threadIdx.x;
    const float* a = d_Asum + b * LLEN + p;
    float mn = a[0], mx = a[0];
    #pragma unroll
    for (int w = 1; w < 5; ++w) { float v = a[w]; mn = fminf(mn, v); mx = fmaxf(mx, v); }
    smn[b] = mn; smx[b] = mx;
    __syncthreads();
    for (int sft = 128; sft > 0; sft >>= 1) {
        if (b < sft) {
            smn[b] = fminf(smn[b], smn[b + sft]);
            smx[b] = fmaxf(smx[b], smx[b + sft]);
        }
        __syncthreads();
    }
    if (b == 0) d_cmp[p] = 0.8f * smn[0] + 0.8f * smx[0];
}

// ---------------- zero pooled ----------------
__global__ void k_zero() {
    int i = blockIdx.x * blockDim.x + threadIdx.x;
    if (i < BB * 300) d_pooled[i] = 0u;
}

// ---------------- K5: conv via mma.sync bf16, cp.async B pipeline ----------
// R11 config restored: 192 thr = 6 warps x m16, 96-t tile, 13 n-tiles/warp.
#define EP2 60
#define NBUF 4
__global__ void __launch_bounds__(192, 4) k_conv_mma(
    const int* __restrict__ gtext, const float* __restrict__ emb,
    const float* __restrict__ cb1, const float* __restrict__ cb2,
    const float* __restrict__ cb3) {
    __shared__ __align__(16) uint32_t EgS[98 * EP2];    // 23520 B
    __shared__ __align__(16) uint32_t Bs[NBUF][832];    // 13312 B
    __shared__ float sBias[3][104];
    int tid = threadIdx.x, lane = tid & 31, wid = tid >> 5;
    int t0 = blockIdx.x * 96, b = blockIdx.y;

    const float* cbs[3] = {cb1, cb2, cb3};
    for (int u = tid; u < 312; u += 192) {
        int g = u / 104, f = u - g * 104;
        sBias[g][f] = (f < 100) ? cbs[g][f] : 0.f;
    }
    // E tile rows t0..t0+97 as bf16x2, pair-interleaved within 8-pair blocks
    for (int r = wid; r < 98; r += 6) {
        int gt = t0 + r;
        const float* er = (gt < LGG) ? emb + (long)gtext[b * LGG + gt] * DM : 0;
        for (int qq = lane; qq < 56; qq += 32) {
            int c0 = 2 * qq;
            float v0 = (er && c0 < 100) ? er[c0] : 0.f;
            float v1 = (er && c0 + 1 < 100) ? er[c0 + 1] : 0.f;
            int bq = qq & 7;
            int p = (bq < 4) ? 2 * bq : 2 * (bq - 4) + 1;
            EgS[r * EP2 + (qq & ~7) + p] = pack_bf16(v0, v1);
        }
    }

    uint32_t bs_base[NBUF];
    #pragma unroll
    for (int j = 0; j < NBUF; ++j) bs_base[j] = smem_u32p(&Bs[j][0]);
    int chunk = tid;
    #pragma unroll
    for (int j = 0; j < 3; ++j) {                       // prologue: slices 0..2
        if (chunk < 208) cp_async16(bs_base[j] + chunk * 16, &d_wbf[j * 832 + chunk * 4]);
        if (tid < 16)    cp_async16(bs_base[j] + (192 + tid) * 16,
                                    &d_wbf[j * 832 + (192 + tid) * 4]);
        cp_commit();
    }

    int q = 0;
    for (int g = 0; g < 3; ++g) {
        float acc[13][4];
        #pragma unroll
        for (int nt = 0; nt < 13; ++nt)
            #pragma unroll
            for (int j = 0; j < 4; ++j) acc[nt][j] = 0.f;
        int ns = (g + 1) * 7;
        for (int i = 0; i < ns; ++i, ++q) {
            cp_wait<2>();
            __syncthreads();
            {                            // issue slice q+3
                int jn = q + 3;
                if (jn < 42) {
                    uint32_t sb = bs_base[jn & 3];
                    const uint32_t* gp = &d_wbf[jn * 832];
                    cp_async16(sb + chunk * 16, gp + chunk * 4);
                    if (tid < 16) cp_async16(sb + (192 + tid) * 16, gp + (192 + tid) * 4);
                }
                cp_commit();
            }
            const uint32_t* Bcur = &Bs[q & 3][0];
            int s = i / 7, ks = i - s * 7;
            int r0 = wid * 16 + (lane >> 2) + s;
            int ab = ks * 8 + 2 * (lane & 3);
            uint2 aLo = *reinterpret_cast<const uint2*>(&EgS[r0 * EP2 + ab]);
            uint2 aHi = *reinterpret_cast<const uint2*>(&EgS[(r0 + 8) * EP2 + ab]);
            const uint32_t* bp = Bcur + (lane >> 2) * 8 + 2 * (lane & 3);
            #pragma unroll
            for (int nt = 0; nt < 13; ++nt) {
                uint2 bv = *reinterpret_cast<const uint2*>(bp + nt * 64);
                mma16n8k16(acc[nt], aLo.x, aHi.x, aLo.y, aHi.y, bv.x, bv.y);
            }
        }
        // ---- epilogue for group g ----
        int Ts = LGG - g;
        int tA = t0 + wid * 16 + (lane >> 2);
        int tB = tA + 8;
        unsigned* pool = d_pooled + b * 300 + g * 100;
        #pragma unroll
        for (int nt = 0; nt < 13; ++nt) {
            float v0 = (tA < Ts) ? acc[nt][0] : -1e30f;
            float v1 = (tA < Ts) ? acc[nt][1] : -1e30f;
            float v2 = (tB < Ts) ? acc[nt][2] : -1e30f;
            float v3 = (tB < Ts) ? acc[nt][3] : -1e30f;
            v0 = fmaxf(v0, v2);
            v1 = fmaxf(v1, v3);
            #pragma unroll
            for (int off = 16; off >= 4; off >>= 1) {
                v0 = fmaxf(v0, __shfl_xor_sync(0xffffffffu, v0, off));
                v1 = fmaxf(v1, __shfl_xor_sync(0xffffffffu, v1, off));
            }
            if (lane < 4) {
                int f0 = nt * 8 + lane * 2;
                float r0v = fmaxf(v0 + sBias[g][f0], 0.f);
                float r1v = fmaxf(v1 + sBias[g][f0 + 1], 0.f);
                if (f0 < 100)     atomicMax(&pool[f0],     __float_as_uint(r0v));
                if (f0 + 1 < 100) atomicMax(&pool[f0 + 1], __float_as_uint(r1v));
            }
        }
    }
}

// ---------------- K6: fused scan + local + global + fin (per batch row) ----
__global__ void __launch_bounds__(512) k_tail(
    const int* __restrict__ ltext, const float* __restrict__ emb,
    const float* __restrict__ att2_w, const float* __restrict__ att2_b,
    const float* __restrict__ mf_w, const float* __restrict__ mf_b,
    const float* __restrict__ fin_w, const float* __restrict__ fin_b) {
    __shared__ int   toks[SCAN_KEEP];
    __shared__ float jflag[SCAN_KEEP];
    __shared__ float twr[DM];
    __shared__ float combine[200];
    __shared__ float ps[300];
    int b = blockIdx.x, tid = threadIdx.x;

    if (tid < SCAN_KEEP) {
        int p = SCAN_START + tid;
        toks[tid]  = ltext[b * LLEN + p + 2];
        jflag[tid] = (d_Tsum[b * LLEN + p + 2] > d_cmp[p]) ? 1.f : 0.f;
    }
    for (int u = tid; u < 300; u += 512)
        ps[u] = __uint_as_float(d_pooled[b * 300 + u]);
    __syncthreads();

    if (tid < DM) {                     // scan -> tw (fp32-exact truncation)
        const float r = 1.0f / 411.0f;
        float tw = 0.f;
        #pragma unroll 8
        for (int i = 0; i < SCAN_KEEP; ++i) {
            float e = emb[(long)toks[i] * DM + tid] * jflag[i];
            tw = (tw + e) * r;
        }
        twr[tid] = tw;
    } else if (tid >= 128 && tid < 228) {  // global_units (independent of tw)
        int f = tid - 128;
        float acc = mf_b[f];
        const float* wr = mf_w + f * 300;
        #pragma unroll 4
        for (int i = 0; i < 300; ++i) acc += ps[i] * wr[i];
        combine[100 + f] = acc;
    }
    __syncthreads();

    if (tid < DM) {                     // local_units
        float acc = att2_b[tid];
        const float* wr = att2_w + tid * DM;
        #pragma unroll 4
        for (int d = 0; d < DM; ++d) acc += twr[d] * wr[d];
        combine[tid] = acc;
    }
    __syncthreads();

    if (tid < 400) {                    // hidden = relu(combine @ fin_w.T + b)
        float acc = fin_b[tid];
        const float* wr = fin_w + tid * 200;
        #pragma unroll 4
        for (int d = 0; d < 200; ++d) acc += combine[d] * wr[d];
        d_hidden[b * 400 + tid] = fmaxf(acc, 0.f);
    }
}

// ---------------- K8: out = hidden @ fin2_w.T + b ----------------
__global__ void __launch_bounds__(512) k_out(const float* __restrict__ fw,
                                             const float* __restrict__ fb,
                                             float* __restrict__ out) {
    __shared__ float hs[64 * 100];
    int c0 = blockIdx.x * 128;
    int b0 = blockIdx.y * 64;
    int tid = threadIdx.x;
    int ci = tid & 127, bg = tid >> 7;
    int c = c0 + ci;
    bool cvalid = (c < NCLS);

    unsigned long long acc[16];
    #pragma unroll
    for (int i = 0; i < 16; ++i) acc[i] = 0ull;

    for (int p = 0; p < 4; ++p) {
        __syncthreads();
        for (int u = tid; u < 64 * 100; u += 512)
            hs[u] = d_hidden[(b0 + u / 100) * 400 + p * 100 + (u % 100)];
        __syncthreads();
        if (cvalid) {
            const float* wr = fw + (long)c * 400 + p * 100;
            const float* hb = hs + bg * 16 * 100;
            for (int h = 0; h < 100; h += 2) {
                unsigned long long wv = *reinterpret_cast<const unsigned long long*>(wr + h);
                #pragma unroll
                for (int i = 0; i < 16; ++i) {
                    unsigned long long hv =
                        *reinterpret_cast<const unsigned long long*>(hb + i * 100 + h);
                    acc[i] = ffma2(wv, hv, acc[i]);
                }
            }
        }
    }
    if (cvalid) {
        float bias = fb[c];
        #pragma unroll
        for (int i = 0; i < 16; ++i)
            out[(long)(b0 + bg * 16 + i) * NCLS + c] = acc2_sum(acc[i]) + bias;
    }
}

// ---------------- launcher ----------------
extern "C" void kernel_launch(void* const* d_in, const int* in_sizes, int n_in,
                              void* d_out, int out_size) {
    const int*   ltext  = (const int*)d_in[0];
    const int*   gtext  = (const int*)d_in[1];
    const float* emb    = (const float*)d_in[2];
    const float* att_w  = (const float*)d_in[3];
    const float* att_b  = (const float*)d_in[4];
    const float* att2_w = (const float*)d_in[5];
    const float* att2_b = (const float*)d_in[6];
    const float* c1w    = (const float*)d_in[7];
    const float* c1b    = (const float*)d_in[8];
    const float* c2w    = (const float*)d_in[9];
    const float* c2b    = (const float*)d_in[10];
    const float* c3w    = (const float*)d_in[11];
    const float* c3b    = (const float*)d_in[12];
    const float* mfw    = (const float*)d_in[13];
    const float* mfb    = (const float*)d_in[14];
    const float* finw   = (const float*)d_in[15];
    const float* finb   = (const float*)d_in[16];
    const float* f2w    = (const float*)d_in[17];
    const float* f2b    = (const float*)d_in[18];
    float* out = (float*)d_out;

    k_zero<<<300, 256>>>();
    k_wprep<<<(42 * 832 + 255) / 256, 256>>>(c1w, c2w, c3w);
    k_token<<<(BB * TOKP + 3) / 4, 128>>>(ltext, emb, att_w, att_b);
    k_conv_mma<<<dim3(5, BB), 192>>>(gtext, emb, c1b, c2b, c3b);
    k_cmp<<<SCAN_KEEP, 256>>>();
    k_tail<<<BB, 512>>>(ltext, emb, att2_w, att2_b, mfw, mfb, finw, finb);
    k_out<<<dim3(24, 4), 512>>>(f2w, f2b, out);
}

// round 14
// speedup vs baseline: 1.8184x; 1.2041x over previous
#include <cuda_runtime.h>
#include <math.h>
#include <stdint.h>

#define BB   256
#define DM   100
#define LLEN 415
#define LGG  411
#define PP   411
#define NF   100
#define NCLS 2987

#define QSCALE 12700.0f
#define QINV   (1.0f / (12700.0f * 12700.0f))

// ---------------- scratch (device globals; no allocation) ----------------
__device__ float    d_Asum[BB * LLEN];
__device__ float    d_Tsum[BB * LLEN];
__device__ float    d_cmp[PP];
__device__ unsigned d_pooled[BB * 300];
__device__ float    d_hidden[BB * 400];
__device__ __align__(16) uint32_t d_wq[21 * 832];   // pre-quantized W slices (s8x4)

// packed f32x2 FMA
__device__ __forceinline__ unsigned long long ffma2(unsigned long long a,
                                                    unsigned long long b,
                                                    unsigned long long c) {
    unsigned long long d;
    asm("fma.rn.f32x2 %0, %1, %2, %3;" : "=l"(d) : "l"(a), "l"(b), "l"(c));
    return d;
}
__device__ __forceinline__ float acc2_sum(unsigned long long a) {
    return __uint_as_float((unsigned)(a & 0xffffffffull)) +
           __uint_as_float((unsigned)(a >> 32));
}
__device__ __forceinline__ uint32_t packq4(float v0, float v1, float v2, float v3) {
    int q0 = __float2int_rn(v0 * QSCALE) & 255;
    int q1 = __float2int_rn(v1 * QSCALE) & 255;
    int q2 = __float2int_rn(v2 * QSCALE) & 255;
    int q3 = __float2int_rn(v3 * QSCALE) & 255;
    return (uint32_t)(q0 | (q1 << 8) | (q2 << 16) | (q3 << 24));
}
__device__ __forceinline__ void mma16n8k32s8(int* c, uint32_t a0, uint32_t a1,
                                             uint32_t a2, uint32_t a3,
                                             uint32_t b0, uint32_t b1) {
    asm volatile(
        "mma.sync.aligned.m16n8k32.row.col.s32.s8.s8.s32 "
        "{%0,%1,%2,%3}, {%4,%5,%6,%7}, {%8,%9}, {%0,%1,%2,%3};"
        : "+r"(c[0]), "+r"(c[1]), "+r"(c[2]), "+r"(c[3])
        : "r"(a0), "r"(a1), "r"(a2), "r"(a3), "r"(b0), "r"(b1));
}
__device__ __forceinline__ uint32_t smem_u32p(const void* p) {
    return (uint32_t)__cvta_generic_to_shared(p);
}
__device__ __forceinline__ void cp_async16(uint32_t saddr, const void* g) {
    asm volatile("cp.async.cg.shared.global [%0], [%1], 16;"
                 :: "r"(saddr), "l"(g) : "memory");
}
__device__ __forceinline__ void cp_commit() {
    asm volatile("cp.async.commit_group;" ::: "memory");
}
template <int N>
__device__ __forceinline__ void cp_wait() {
    asm volatile("cp.async.wait_group %0;" :: "n"(N) : "memory");
}

#define SCAN_KEEP 64
#define SCAN_START (PP - SCAN_KEEP)   // 347
#define TOKP (SCAN_KEEP + 4)          // 68 positions: 347..414

// ---------------- K0: pre-quantize W to s8x4 slice layout ----------------
// 21 slices: g0 chunks 0..3, g1 chunks 0..6, g2 chunks 0..9. flat k = s*100+k
// (= natural weight layout). Slice: [nt 0..12][f' 0..7][pairpos 0..7] u32;
// pairpos interleave: kg<4 -> 2*kg, else 2*(kg-4)+1 (uint2 b0/b1 loads).
__global__ void k_wprep(const float* __restrict__ w1, const float* __restrict__ w2,
                        const float* __restrict__ w3) {
    int idx = blockIdx.x * blockDim.x + threadIdx.x;
    if (idx >= 21 * 832) return;
    int q = idx / 832, r = idx - q * 832;
    int g = (q < 4) ? 0 : (q < 11) ? 1 : 2;
    int chunk = q - ((g == 0) ? 0 : (g == 1) ? 4 : 11);
    int Kg = (g + 1) * 100;
    const float* w = (g == 0) ? w1 : (g == 1) ? w2 : w3;
    int nt = r >> 6, rem = r & 63, fp = rem >> 3, pos = rem & 7;
    int kg = (pos & 1) ? (pos >> 1) + 4 : (pos >> 1);
    int flat = chunk * 32 + kg * 4;
    int f = nt * 8 + fp;
    float v[4];
    #pragma unroll
    for (int j = 0; j < 4; ++j) {
        int fl = flat + j;
        v[j] = (f < 100 && fl < Kg) ? w[f * Kg + fl] : 0.f;
    }
    d_wq[idx] = packq4(v[0], v[1], v[2], v[3]);
}

// ---------------- K1: per-token Asum + row-sum (positions 347..414 only) ----
__global__ void k_token(const int* __restrict__ ltext, const float* __restrict__ emb,
                        const float* __restrict__ att_w, const float* __restrict__ att_b) {
    int warp = (blockIdx.x * blockDim.x + threadIdx.x) >> 5;
    int lane = threadIdx.x & 31;
    if (warp >= BB * TOKP) return;
    int b = warp / TOKP;
    int pos = SCAN_START + (warp - b * TOKP);
    int tok = ltext[b * LLEN + pos];
    const float* er = emb + (long)tok * DM;
    float s[5] = {0.f, 0.f, 0.f, 0.f, 0.f};
    float ts = 0.f;
    for (int d = lane; d < DM; d += 32) {
        float e = er[d];
        ts += e;
        s[0] += e * att_w[0 * DM + d];
        s[1] += e * att_w[1 * DM + d];
        s[2] += e * att_w[2 * DM + d];
        s[3] += e * att_w[3 * DM + d];
        s[4] += e * att_w[4 * DM + d];
    }
    #pragma unroll
    for (int o = 16; o > 0; o >>= 1) {
        #pragma unroll
        for (int w = 0; w < 5; ++w) s[w] += __shfl_down_sync(0xffffffffu, s[w], o);
        ts += __shfl_down_sync(0xffffffffu, ts, o);
    }
    if (lane == 0) {
        float a = 0.f;
        #pragma unroll
        for (int w = 0; w < 5; ++w) a += tanhf(s[w] + att_b[w]);
        d_Asum[b * LLEN + pos] = a;
        d_Tsum[b * LLEN + pos] = ts;
    }
}

// ---------------- K2: comparison[p], p in 347..410 only ----------------
__global__ void k_cmp() {
    __shared__ float smn[256], smx[256];
    int p = SCAN_START + blockIdx.x;
    int b = threadIdx.x;
    const float* a = d_Asum + b * LLEN + p;
    float mn = a[0], mx = a[0];
    #pragma unroll
    for (int w = 1; w < 5; ++w) { float v = a[w]; mn = fminf(mn, v); mx = fmaxf(mx, v); }
    smn[b] = mn; smx[b] = mx;
    __syncthreads();
    for (int sft = 128; sft > 0; sft >>= 1) {
        if (b < sft) {
            smn[b] = fminf(smn[b], smn[b + sft]);
            smx[b] = fmaxf(smx[b], smx[b + sft]);
        }
        __syncthreads();
    }
    if (b == 0) d_cmp[p] = 0.8f * smn[0] + 0.8f * smx[0];
}

// ---------------- zero pooled ----------------
__global__ void k_zero() {
    int i = blockIdx.x * blockDim.x + threadIdx.x;
    if (i < BB * 300) d_pooled[i] = 0u;
}

// ---------------- K5: conv via mma.sync s8 (m16n8k32), shift folded into K --
// 192 thr = 6 warps x m16, 96-t tile, 13 n-tiles/warp. 21 slices (flat-K
// chunks of 32). A: int8 E rows in smem, pitch 36 u32; lane (s,k) decomposed
// from flat addr. Exact s32 accumulation; epilogue scales by QINV.
#define EPQ 36
#define NBUF 4
__global__ void __launch_bounds__(192, 4) k_conv_mma(
    const int* __restrict__ gtext, const float* __restrict__ emb,
    const float* __restrict__ cb1, const float* __restrict__ cb2,
    const float* __restrict__ cb3) {
    __shared__ __align__(16) uint32_t EgS[98 * EPQ];    // 14112 B
    __shared__ __align__(16) uint32_t Bs[NBUF][832];    // 13312 B
    __shared__ float sBias[3][104];
    __shared__ int   sToks[98];
    int tid = threadIdx.x, lane = tid & 31, wid = tid >> 5;
    int t0 = blockIdx.x * 96, b = blockIdx.y;

    const float* cbs[3] = {cb1, cb2, cb3};
    for (int u = tid; u < 312; u += 192) {
        int g = u / 104, f = u - g * 104;
        sBias[g][f] = (f < 100) ? cbs[g][f] : 0.f;
    }
    if (tid < 98) {
        int gt = t0 + tid;
        sToks[tid] = (gt < LGG) ? gtext[b * LGG + gt] : -1;
    }
    __syncthreads();
    // E tile: quantize to s8x4, rows 0..97, kg 0..24 (k = kg*4..+3)
    for (int u = tid; u < 98 * 25; u += 192) {
        int r = u / 25, kg = u - r * 25;
        int tok = sToks[r];
        uint32_t packed = 0;
        if (tok >= 0) {
            float4 f = *reinterpret_cast<const float4*>(emb + (long)tok * DM + kg * 4);
            packed = packq4(f.x, f.y, f.z, f.w);
        }
        EgS[r * EPQ + kg] = packed;
    }

    uint32_t bs_base[NBUF];
    #pragma unroll
    for (int j = 0; j < NBUF; ++j) bs_base[j] = smem_u32p(&Bs[j][0]);
    int chunk = tid;
    #pragma unroll
    for (int j = 0; j < 3; ++j) {                       // prologue: slices 0..2
        if (chunk < 208) cp_async16(bs_base[j] + chunk * 16, &d_wq[j * 832 + chunk * 4]);
        if (tid < 16)    cp_async16(bs_base[j] + (192 + tid) * 16,
                                    &d_wq[j * 832 + (192 + tid) * 4]);
        cp_commit();
    }

    int rowbase = (wid * 16 + (lane >> 2)) * EPQ;
    int cb4 = (lane & 3) << 2;
    const int nsArr[3] = {4, 7, 10};

    int q = 0;
    for (int g = 0; g < 3; ++g) {
        int acc[13][4];
        #pragma unroll
        for (int nt = 0; nt < 13; ++nt)
            #pragma unroll
            for (int j = 0; j < 4; ++j) acc[nt][j] = 0;
        int ns = nsArr[g];
        for (int i = 0; i < ns; ++i, ++q) {
            cp_wait<2>();
            __syncthreads();
            {                            // issue slice q+3
                int jn = q + 3;
                if (jn < 21) {
                    uint32_t sb = bs_base[jn & 3];
                    const uint32_t* gp = &d_wq[jn * 832];
                    cp_async16(sb + chunk * 16, gp + chunk * 4);
                    if (tid < 16) cp_async16(sb + (192 + tid) * 16, gp + (192 + tid) * 4);
                }
                cp_commit();
            }
            const uint32_t* Bcur = &Bs[q & 3][0];
            // A fragments: flat k -> (shift s, col k) folded into address
            int flat0 = (i << 5) + cb4;
            int flat1 = flat0 + 16;
            int s0 = (flat0 >= 100) + (flat0 >= 200);
            int s1 = (flat1 >= 100) + (flat1 >= 200);
            int idx0 = (flat0 >> 2) + s0 * (EPQ - 25);
            int idx1 = (flat1 >> 2) + s1 * (EPQ - 25);
            uint32_t a0 = EgS[rowbase + idx0];
            uint32_t a1 = EgS[rowbase + 8 * EPQ + idx0];
            uint32_t a2 = EgS[rowbase + idx1];
            uint32_t a3 = EgS[rowbase + 8 * EPQ + idx1];
            const uint32_t* bp = Bcur + (lane >> 2) * 8 + 2 * (lane & 3);
            #pragma unroll
            for (int nt = 0; nt < 13; ++nt) {
                uint2 bv = *reinterpret_cast<const uint2*>(bp + nt * 64);
                mma16n8k32s8(acc[nt], a0, a1, a2, a3, bv.x, bv.y);
            }
        }
        // ---- epilogue for group g ----
        int Ts = LGG - g;
        int tA = t0 + wid * 16 + (lane >> 2);
        int tB = tA + 8;
        unsigned* pool = d_pooled + b * 300 + g * 100;
        #pragma unroll
        for (int nt = 0; nt < 13; ++nt) {
            float v0 = (tA < Ts) ? (float)acc[nt][0] * QINV : -1e30f;
            float v1 = (tA < Ts) ? (float)acc[nt][1] * QINV : -1e30f;
            float v2 = (tB < Ts) ? (float)acc[nt][2] * QINV : -1e30f;
            float v3 = (tB < Ts) ? (float)acc[nt][3] * QINV : -1e30f;
            v0 = fmaxf(v0, v2);
            v1 = fmaxf(v1, v3);
            #pragma unroll
            for (int off = 16; off >= 4; off >>= 1) {
                v0 = fmaxf(v0, __shfl_xor_sync(0xffffffffu, v0, off));
                v1 = fmaxf(v1, __shfl_xor_sync(0xffffffffu, v1, off));
            }
            if (lane < 4) {
                int f0 = nt * 8 + lane * 2;
                float r0v = fmaxf(v0 + sBias[g][f0], 0.f);
                float r1v = fmaxf(v1 + sBias[g][f0 + 1], 0.f);
                if (f0 < 100)     atomicMax(&pool[f0],     __float_as_uint(r0v));
                if (f0 + 1 < 100) atomicMax(&pool[f0 + 1], __float_as_uint(r1v));
            }
        }
    }
}

// ---------------- K6: fused scan + local + global + fin (per batch row) ----
__global__ void __launch_bounds__(512) k_tail(
    const int* __restrict__ ltext, const float* __restrict__ emb,
    const float* __restrict__ att2_w, const float* __restrict__ att2_b,
    const float* __restrict__ mf_w, const float* __restrict__ mf_b,
    const float* __restrict__ fin_w, const float* __restrict__ fin_b) {
    __shared__ int   toks[SCAN_KEEP];
    __shared__ float jflag[SCAN_KEEP];
    __shared__ float twr[DM];
    __shared__ float combine[200];
    __shared__ float ps[300];
    int b = blockIdx.x, tid = threadIdx.x;

    if (tid < SCAN_KEEP) {
        int p = SCAN_START + tid;
        toks[tid]  = ltext[b * LLEN + p + 2];
        jflag[tid] = (d_Tsum[b * LLEN + p + 2] > d_cmp[p]) ? 1.f : 0.f;
    }
    for (int u = tid; u < 300; u += 512)
        ps[u] = __uint_as_float(d_pooled[b * 300 + u]);
    __syncthreads();

    if (tid < DM) {                     // scan -> tw (fp32-exact truncation)
        const float r = 1.0f / 411.0f;
        float tw = 0.f;
        #pragma unroll 8
        for (int i = 0; i < SCAN_KEEP; ++i) {
            float e = emb[(long)toks[i] * DM + tid] * jflag[i];
            tw = (tw + e) * r;
        }
        twr[tid] = tw;
    } else if (tid >= 128 && tid < 228) {  // global_units (independent of tw)
        int f = tid - 128;
        float acc = mf_b[f];
        const float* wr = mf_w + f * 300;
        #pragma unroll 4
        for (int i = 0; i < 300; ++i) acc += ps[i] * wr[i];
        combine[100 + f] = acc;
    }
    __syncthreads();

    if (tid < DM) {                     // local_units
        float acc = att2_b[tid];
        const float* wr = att2_w + tid * DM;
        #pragma unroll 4
        for (int d = 0; d < DM; ++d) acc += twr[d] * wr[d];
        combine[tid] = acc;
    }
    __syncthreads();

    if (tid < 400) {                    // hidden = relu(combine @ fin_w.T + b)
        float acc = fin_b[tid];
        const float* wr = fin_w + tid * 200;
        #pragma unroll 4
        for (int d = 0; d < 200; ++d) acc += combine[d] * wr[d];
        d_hidden[b * 400 + tid] = fmaxf(acc, 0.f);
    }
}

// ---------------- K8: out = hidden @ fin2_w.T + b ----------------
__global__ void __launch_bounds__(512) k_out(const float* __restrict__ fw,
                                             const float* __restrict__ fb,
                                             float* __restrict__ out) {
    __shared__ float hs[64 * 100];
    int c0 = blockIdx.x * 128;
    int b0 = blockIdx.y * 64;
    int tid = threadIdx.x;
    int ci = tid & 127, bg = tid >> 7;
    int c = c0 + ci;
    bool cvalid = (c < NCLS);

    unsigned long long acc[16];
    #pragma unroll
    for (int i = 0; i < 16; ++i) acc[i] = 0ull;

    for (int p = 0; p < 4; ++p) {
        __syncthreads();
        for (int u = tid; u < 64 * 100; u += 512)
            hs[u] = d_hidden[(b0 + u / 100) * 400 + p * 100 + (u % 100)];
        __syncthreads();
        if (cvalid) {
            const float* wr = fw + (long)c * 400 + p * 100;
            const float* hb = hs + bg * 16 * 100;
            for (int h = 0; h < 100; h += 2) {
                unsigned long long wv = *reinterpret_cast<const unsigned long long*>(wr + h);
                #pragma unroll
                for (int i = 0; i < 16; ++i) {
                    unsigned long long hv =
                        *reinterpret_cast<const unsigned long long*>(hb + i * 100 + h);
                    acc[i] = ffma2(wv, hv, acc[i]);
                }
            }
        }
    }
    if (cvalid) {
        float bias = fb[c];
        #pragma unroll
        for (int i = 0; i < 16; ++i)
            out[(long)(b0 + bg * 16 + i) * NCLS + c] = acc2_sum(acc[i]) + bias;
    }
}

// ---------------- launcher ----------------
extern "C" void kernel_launch(void* const* d_in, const int* in_sizes, int n_in,
                              void* d_out, int out_size) {
    const int*   ltext  = (const int*)d_in[0];
    const int*   gtext  = (const int*)d_in[1];
    const float* emb    = (const float*)d_in[2];
    const float* att_w  = (const float*)d_in[3];
    const float* att_b  = (const float*)d_in[4];
    const float* att2_w = (const float*)d_in[5];
    const float* att2_b = (const float*)d_in[6];
    const float* c1w    = (const float*)d_in[7];
    const float* c1b    = (const float*)d_in[8];
    const float* c2w    = (const float*)d_in[9];
    const float* c2b    = (const float*)d_in[10];
    const float* c3w    = (const float*)d_in[11];
    const float* c3b    = (const float*)d_in[12];
    const float* mfw    = (const float*)d_in[13];
    const float* mfb    = (const float*)d_in[14];
    const float* finw   = (const float*)d_in[15];
    const float* finb   = (const float*)d_in[16];
    const float* f2w    = (const float*)d_in[17];
    const float* f2b    = (const float*)d_in[18];
    float* out = (float*)d_out;

    k_zero<<<300, 256>>>();
    k_wprep<<<(21 * 832 + 255) / 256, 256>>>(c1w, c2w, c3w);
    k_token<<<(BB * TOKP + 3) / 4, 128>>>(ltext, emb, att_w, att_b);
    k_conv_mma<<<dim3(5, BB), 192>>>(gtext, emb, c1b, c2b, c3b);
    k_cmp<<<SCAN_KEEP, 256>>>();
    k_tail<<<BB, 512>>>(ltext, emb, att2_w, att2_b, mfw, mfb, finw, finb);
    k_out<<<dim3(24, 4), 512>>>(f2w, f2b, out);
}

// round 15
// speedup vs baseline: 2.4663x; 1.3563x over previous
#include <cuda_runtime.h>
#include <math.h>
#include <stdint.h>

#define BB   256
#define DM   100
#define LLEN 415
#define LGG  411
#define PP   411
#define NF   100
#define NCLS 2987

#define QSCALE 12700.0f
#define QINV   (1.0f / (12700.0f * 12700.0f))

// ---------------- scratch (device globals; no allocation) ----------------
__device__ float    d_Asum[BB * LLEN];
__device__ float    d_Tsum[BB * LLEN];
__device__ float    d_cmp[PP];
__device__ unsigned d_pooled[BB * 300];
__device__ __align__(16) uint32_t d_wq[21 * 832];       // s8 conv W slices
__device__ __align__(16) uint32_t d_hbf[25 * 32 * 64];  // hidden bf16x2 B-frag layout
__device__ __align__(16) uint32_t d_w2bf[3072 * 200];   // fin2_w bf16x2 A-frag rows

// packed f32x2 FMA
__device__ __forceinline__ unsigned long long ffma2(unsigned long long a,
                                                    unsigned long long b,
                                                    unsigned long long c) {
    unsigned long long d;
    asm("fma.rn.f32x2 %0, %1, %2, %3;" : "=l"(d) : "l"(a), "l"(b), "l"(c));
    return d;
}
__device__ __forceinline__ uint32_t pack_bf16(float lo, float hi) {
    uint32_t r;
    asm("cvt.rn.bf16x2.f32 %0, %1, %2;" : "=r"(r) : "f"(hi), "f"(lo));
    return r;
}
__device__ __forceinline__ uint32_t packq4(float v0, float v1, float v2, float v3) {
    int q0 = __float2int_rn(v0 * QSCALE) & 255;
    int q1 = __float2int_rn(v1 * QSCALE) & 255;
    int q2 = __float2int_rn(v2 * QSCALE) & 255;
    int q3 = __float2int_rn(v3 * QSCALE) & 255;
    return (uint32_t)(q0 | (q1 << 8) | (q2 << 16) | (q3 << 24));
}
__device__ __forceinline__ void mma16n8k32s8(int* c, uint32_t a0, uint32_t a1,
                                             uint32_t a2, uint32_t a3,
                                             uint32_t b0, uint32_t b1) {
    asm volatile(
        "mma.sync.aligned.m16n8k32.row.col.s32.s8.s8.s32 "
        "{%0,%1,%2,%3}, {%4,%5,%6,%7}, {%8,%9}, {%0,%1,%2,%3};"
        : "+r"(c[0]), "+r"(c[1]), "+r"(c[2]), "+r"(c[3])
        : "r"(a0), "r"(a1), "r"(a2), "r"(a3), "r"(b0), "r"(b1));
}
__device__ __forceinline__ void mma16n8k16bf(float* c, uint32_t a0, uint32_t a1,
                                             uint32_t a2, uint32_t a3,
                                             uint32_t b0, uint32_t b1) {
    asm volatile(
        "mma.sync.aligned.m16n8k16.row.col.f32.bf16.bf16.f32 "
        "{%0,%1,%2,%3}, {%4,%5,%6,%7}, {%8,%9}, {%0,%1,%2,%3};"
        : "+f"(c[0]), "+f"(c[1]), "+f"(c[2]), "+f"(c[3])
        : "r"(a0), "r"(a1), "r"(a2), "r"(a3), "r"(b0), "r"(b1));
}
__device__ __forceinline__ uint32_t smem_u32p(const void* p) {
    return (uint32_t)__cvta_generic_to_shared(p);
}
__device__ __forceinline__ void cp_async16(uint32_t saddr, const void* g) {
    asm volatile("cp.async.cg.shared.global [%0], [%1], 16;"
                 :: "r"(saddr), "l"(g) : "memory");
}
__device__ __forceinline__ void cp_commit() {
    asm volatile("cp.async.commit_group;" ::: "memory");
}
template <int N>
__device__ __forceinline__ void cp_wait() {
    asm volatile("cp.async.wait_group %0;" :: "n"(N) : "memory");
}

#define SCAN_KEEP 64
#define SCAN_START (PP - SCAN_KEEP)   // 347
#define TOKP (SCAN_KEEP + 4)          // 68 positions: 347..414

// ---------------- K0a: pre-quantize conv W to s8x4 slice layout ------------
__global__ void k_wprep(const float* __restrict__ w1, const float* __restrict__ w2,
                        const float* __restrict__ w3) {
    int idx = blockIdx.x * blockDim.x + threadIdx.x;
    if (idx >= 21 * 832) return;
    int q = idx / 832, r = idx - q * 832;
    int g = (q < 4) ? 0 : (q < 11) ? 1 : 2;
    int chunk = q - ((g == 0) ? 0 : (g == 1) ? 4 : 11);
    int Kg = (g + 1) * 100;
    const float* w = (g == 0) ? w1 : (g == 1) ? w2 : w3;
    int nt = r >> 6, rem = r & 63, fp = rem >> 3, pos = rem & 7;
    int kg = (pos & 1) ? (pos >> 1) + 4 : (pos >> 1);
    int flat = chunk * 32 + kg * 4;
    int f = nt * 8 + fp;
    float v[4];
    #pragma unroll
    for (int j = 0; j < 4; ++j) {
        int fl = flat + j;
        v[j] = (f < 100 && fl < Kg) ? w[f * Kg + fl] : 0.f;
    }
    d_wq[idx] = packq4(v[0], v[1], v[2], v[3]);
}

// ---------------- K0b: fin2_w -> bf16x2 A-fragment rows (padded to 3072) ----
__global__ void k_w2prep(const float* __restrict__ fw) {
    int idx = blockIdx.x * blockDim.x + threadIdx.x;
    if (idx >= 3072 * 200) return;
    int cc = idx / 200, q = idx - cc * 200;        // q = k-pair 0..199
    float v0 = 0.f, v1 = 0.f;
    if (cc < NCLS) {
        v0 = fw[(long)cc * 400 + 2 * q];
        v1 = fw[(long)cc * 400 + 2 * q + 1];
    }
    int bq = q & 7;
    int p = (bq < 4) ? 2 * bq : 2 * (bq - 4) + 1;  // pair interleave in 8-block
    d_w2bf[cc * 200 + (q & ~7) + p] = pack_bf16(v0, v1);
}

// ---------------- K1: per-token Asum + row-sum (positions 347..414 only) ----
__global__ void k_token(const int* __restrict__ ltext, const float* __restrict__ emb,
                        const float* __restrict__ att_w, const float* __restrict__ att_b) {
    int warp = (blockIdx.x * blockDim.x + threadIdx.x) >> 5;
    int lane = threadIdx.x & 31;
    if (warp >= BB * TOKP) return;
    int b = warp / TOKP;
    int pos = SCAN_START + (warp - b * TOKP);
    int tok = ltext[b * LLEN + pos];
    const float* er = emb + (long)tok * DM;
    float s[5] = {0.f, 0.f, 0.f, 0.f, 0.f};
    float ts = 0.f;
    for (int d = lane; d < DM; d += 32) {
        float e = er[d];
        ts += e;
        s[0] += e * att_w[0 * DM + d];
        s[1] += e * att_w[1 * DM + d];
        s[2] += e * att_w[2 * DM + d];
        s[3] += e * att_w[3 * DM + d];
        s[4] += e * att_w[4 * DM + d];
    }
    #pragma unroll
    for (int o = 16; o > 0; o >>= 1) {
        #pragma unroll
        for (int w = 0; w < 5; ++w) s[w] += __shfl_down_sync(0xffffffffu, s[w], o);
        ts += __shfl_down_sync(0xffffffffu, ts, o);
    }
    if (lane == 0) {
        float a = 0.f;
        #pragma unroll
        for (int w = 0; w < 5; ++w) a += tanhf(s[w] + att_b[w]);
        d_Asum[b * LLEN + pos] = a;
        d_Tsum[b * LLEN + pos] = ts;
    }
}

// ---------------- K2: comparison[p], p in 347..410 only ----------------
__global__ void k_cmp() {
    __shared__ float smn[256], smx[256];
    int p = SCAN_START + blockIdx.x;
    int b = threadIdx.x;
    const float* a = d_Asum + b * LLEN + p;
    float mn = a[0], mx = a[0];
    #pragma unroll
    for (int w = 1; w < 5; ++w) { float v = a[w]; mn = fminf(mn, v); mx = fmaxf(mx, v); }
    smn[b] = mn; smx[b] = mx;
    __syncthreads();
    for (int sft = 128; sft > 0; sft >>= 1) {
        if (b < sft) {
            smn[b] = fminf(smn[b], smn[b + sft]);
            smx[b] = fmaxf(smx[b], smx[b + sft]);
        }
        __syncthreads();
    }
    if (b == 0) d_cmp[p] = 0.8f * smn[0] + 0.8f * smx[0];
}

// ---------------- zero pooled ----------------
__global__ void k_zero() {
    int i = blockIdx.x * blockDim.x + threadIdx.x;
    if (i < BB * 300) d_pooled[i] = 0u;
}

// ---------------- K5: conv via mma.sync s8 (m16n8k32), shift folded into K --
#define EPQ 36
#define NBUF 4
__global__ void __launch_bounds__(192, 4) k_conv_mma(
    const int* __restrict__ gtext, const float* __restrict__ emb,
    const float* __restrict__ cb1, const float* __restrict__ cb2,
    const float* __restrict__ cb3) {
    __shared__ __align__(16) uint32_t EgS[98 * EPQ];    // 14112 B
    __shared__ __align__(16) uint32_t Bs[NBUF][832];    // 13312 B
    __shared__ float sBias[3][104];
    __shared__ int   sToks[98];
    int tid = threadIdx.x, lane = tid & 31, wid = tid >> 5;
    int t0 = blockIdx.x * 96, b = blockIdx.y;

    const float* cbs[3] = {cb1, cb2, cb3};
    for (int u = tid; u < 312; u += 192) {
        int g = u / 104, f = u - g * 104;
        sBias[g][f] = (f < 100) ? cbs[g][f] : 0.f;
    }
    if (tid < 98) {
        int gt = t0 + tid;
        sToks[tid] = (gt < LGG) ? gtext[b * LGG + gt] : -1;
    }
    __syncthreads();
    for (int u = tid; u < 98 * 25; u += 192) {
        int r = u / 25, kg = u - r * 25;
        int tok = sToks[r];
        uint32_t packed = 0;
        if (tok >= 0) {
            float4 f = *reinterpret_cast<const float4*>(emb + (long)tok * DM + kg * 4);
            packed = packq4(f.x, f.y, f.z, f.w);
        }
        EgS[r * EPQ + kg] = packed;
    }

    uint32_t bs_base[NBUF];
    #pragma unroll
    for (int j = 0; j < NBUF; ++j) bs_base[j] = smem_u32p(&Bs[j][0]);
    int chunk = tid;
    #pragma unroll
    for (int j = 0; j < 3; ++j) {
        if (chunk < 208) cp_async16(bs_base[j] + chunk * 16, &d_wq[j * 832 + chunk * 4]);
        if (tid < 16)    cp_async16(bs_base[j] + (192 + tid) * 16,
                                    &d_wq[j * 832 + (192 + tid) * 4]);
        cp_commit();
    }

    int rowbase = (wid * 16 + (lane >> 2)) * EPQ;
    int cb4 = (lane & 3) << 2;
    const int nsArr[3] = {4, 7, 10};

    int q = 0;
    for (int g = 0; g < 3; ++g) {
        int acc[13][4];
        #pragma unroll
        for (int nt = 0; nt < 13; ++nt)
            #pragma unroll
            for (int j = 0; j < 4; ++j) acc[nt][j] = 0;
        int ns = nsArr[g];
        for (int i = 0; i < ns; ++i, ++q) {
            cp_wait<2>();
            __syncthreads();
            {
                int jn = q + 3;
                if (jn < 21) {
                    uint32_t sb = bs_base[jn & 3];
                    const uint32_t* gp = &d_wq[jn * 832];
                    cp_async16(sb + chunk * 16, gp + chunk * 4);
                    if (tid < 16) cp_async16(sb + (192 + tid) * 16, gp + (192 + tid) * 4);
                }
                cp_commit();
            }
            const uint32_t* Bcur = &Bs[q & 3][0];
            int flat0 = (i << 5) + cb4;
            int flat1 = flat0 + 16;
            int s0 = (flat0 >= 100) + (flat0 >= 200);
            int s1 = (flat1 >= 100) + (flat1 >= 200);
            int idx0 = (flat0 >> 2) + s0 * (EPQ - 25);
            int idx1 = (flat1 >> 2) + s1 * (EPQ - 25);
            uint32_t a0 = EgS[rowbase + idx0];
            uint32_t a1 = EgS[rowbase + 8 * EPQ + idx0];
            uint32_t a2 = EgS[rowbase + idx1];
            uint32_t a3 = EgS[rowbase + 8 * EPQ + idx1];
            const uint32_t* bp = Bcur + (lane >> 2) * 8 + 2 * (lane & 3);
            #pragma unroll
            for (int nt = 0; nt < 13; ++nt) {
                uint2 bv = *reinterpret_cast<const uint2*>(bp + nt * 64);
                mma16n8k32s8(acc[nt], a0, a1, a2, a3, bv.x, bv.y);
            }
        }
        int Ts = LGG - g;
        int tA = t0 + wid * 16 + (lane >> 2);
        int tB = tA + 8;
        unsigned* pool = d_pooled + b * 300 + g * 100;
        #pragma unroll
        for (int nt = 0; nt < 13; ++nt) {
            float v0 = (tA < Ts) ? (float)acc[nt][0] * QINV : -1e30f;
            float v1 = (tA < Ts) ? (float)acc[nt][1] * QINV : -1e30f;
            float v2 = (tB < Ts) ? (float)acc[nt][2] * QINV : -1e30f;
            float v3 = (tB < Ts) ? (float)acc[nt][3] * QINV : -1e30f;
            v0 = fmaxf(v0, v2);
            v1 = fmaxf(v1, v3);
            #pragma unroll
            for (int off = 16; off >= 4; off >>= 1) {
                v0 = fmaxf(v0, __shfl_xor_sync(0xffffffffu, v0, off));
                v1 = fmaxf(v1, __shfl_xor_sync(0xffffffffu, v1, off));
            }
            if (lane < 4) {
                int f0 = nt * 8 + lane * 2;
                float r0v = fmaxf(v0 + sBias[g][f0], 0.f);
                float r1v = fmaxf(v1 + sBias[g][f0 + 1], 0.f);
                if (f0 < 100)     atomicMax(&pool[f0],     __float_as_uint(r0v));
                if (f0 + 1 < 100) atomicMax(&pool[f0 + 1], __float_as_uint(r1v));
            }
        }
    }
}

// ---------------- K6: fused scan + local + global + fin; packs bf16 hidden --
__global__ void __launch_bounds__(512) k_tail(
    const int* __restrict__ ltext, const float* __restrict__ emb,
    const float* __restrict__ att2_w, const float* __restrict__ att2_b,
    const float* __restrict__ mf_w, const float* __restrict__ mf_b,
    const float* __restrict__ fin_w, const float* __restrict__ fin_b) {
    __shared__ int   toks[SCAN_KEEP];
    __shared__ float jflag[SCAN_KEEP];
    __shared__ float twr[DM];
    __shared__ float combine[200];
    __shared__ float ps[300];
    __shared__ float hid[400];
    int b = blockIdx.x, tid = threadIdx.x;

    if (tid < SCAN_KEEP) {
        int p = SCAN_START + tid;
        toks[tid]  = ltext[b * LLEN + p + 2];
        jflag[tid] = (d_Tsum[b * LLEN + p + 2] > d_cmp[p]) ? 1.f : 0.f;
    }
    for (int u = tid; u < 300; u += 512)
        ps[u] = __uint_as_float(d_pooled[b * 300 + u]);
    __syncthreads();

    if (tid < DM) {                     // scan -> tw (fp32-exact truncation)
        const float r = 1.0f / 411.0f;
        float tw = 0.f;
        #pragma unroll 8
        for (int i = 0; i < SCAN_KEEP; ++i) {
            float e = emb[(long)toks[i] * DM + tid] * jflag[i];
            tw = (tw + e) * r;
        }
        twr[tid] = tw;
    } else if (tid >= 128 && tid < 228) {  // global_units
        int f = tid - 128;
        float acc = mf_b[f];
        const float* wr = mf_w + f * 300;
        #pragma unroll 4
        for (int i = 0; i < 300; ++i) acc += ps[i] * wr[i];
        combine[100 + f] = acc;
    }
    __syncthreads();

    if (tid < DM) {                     // local_units
        float acc = att2_b[tid];
        const float* wr = att2_w + tid * DM;
        #pragma unroll 4
        for (int d = 0; d < DM; ++d) acc += twr[d] * wr[d];
        combine[tid] = acc;
    }
    __syncthreads();

    if (tid < 400) {                    // hidden = relu(combine @ fin_w.T + b)
        float acc = fin_b[tid];
        const float* wr = fin_w + tid * 200;
        #pragma unroll 4
        for (int d = 0; d < 200; ++d) acc += combine[d] * wr[d];
        hid[tid] = fmaxf(acc, 0.f);
    }
    __syncthreads();

    if (tid < 200) {                    // pack bf16x2 into B-frag layout
        int q = tid;
        int c = q >> 3, bq = q & 7;
        int p = (bq < 4) ? 2 * bq : 2 * (bq - 4) + 1;
        uint32_t v = pack_bf16(hid[2 * q], hid[2 * q + 1]);
        d_hbf[((c * 32 + (b >> 3)) * 8 + (b & 7)) * 8 + p] = v;
    }
}

// ---------------- K8: out = hidden @ fin2_w.T + b via bf16 MMA -------------
// M=classes (A = d_w2bf rows), N=batch (B = d_hbf), K=400 (25 k16 chunks).
// CTA: 96 classes (6 warps x m16) x 32 batch (4 n-tiles). Grid 32 x 8.
__global__ void __launch_bounds__(192) k_out_mma(const float* __restrict__ fb,
                                                 float* __restrict__ out) {
    __shared__ __align__(16) uint32_t sB[25 * 4 * 64];   // 25600 B
    __shared__ float sBias[96];
    int tid = threadIdx.x, lane = tid & 31, wid = tid >> 5;
    int c0 = blockIdx.x * 96;
    int b0 = blockIdx.y * 32;
    int bt0 = blockIdx.y * 4;

    if (tid < 96) {
        int c = c0 + tid;
        sBias[tid] = (c < NCLS) ? fb[c] : 0.f;
    }
    // stage hidden tile: 1600 uint4
    {
        uint32_t sbase = smem_u32p(sB);
        for (int i = tid; i < 1600; i += 192) {
            int c = i >> 6, rem = i & 63, btl = rem >> 4, j = rem & 15;
            cp_async16(sbase + (uint32_t)(((c * 4 + btl) * 64 + j * 4) * 4),
                       &d_hbf[(c * 32 + bt0 + btl) * 64 + j * 4]);
        }
        cp_commit();
    }
    cp_wait<0>();
    __syncthreads();

    float acc[4][4];
    #pragma unroll
    for (int nt = 0; nt < 4; ++nt)
        #pragma unroll
        for (int j = 0; j < 4; ++j) acc[nt][j] = 0.f;

    const uint32_t* arow = &d_w2bf[(long)(c0 + wid * 16 + (lane >> 2)) * 200
                                   + 2 * (lane & 3)];
    const uint32_t* bp = &sB[(lane >> 2) * 8 + 2 * (lane & 3)];

    uint2 pLo = *reinterpret_cast<const uint2*>(arow);
    uint2 pHi = *reinterpret_cast<const uint2*>(arow + 8 * 200);
    for (int c = 0; c < 25; ++c) {
        uint2 aLo = pLo, aHi = pHi;
        if (c + 1 < 25) {
            pLo = *reinterpret_cast<const uint2*>(arow + (c + 1) * 8);
            pHi = *reinterpret_cast<const uint2*>(arow + 8 * 200 + (c + 1) * 8);
        }
        const uint32_t* bc = bp + c * 256;
        #pragma unroll
        for (int nt = 0; nt < 4; ++nt) {
            uint2 bv = *reinterpret_cast<const uint2*>(bc + nt * 64);
            mma16n8k16bf(acc[nt], aLo.x, aHi.x, aLo.y, aHi.y, bv.x, bv.y);
        }
    }
    // epilogue: out[batch][class] = acc + bias
    int crA = wid * 16 + (lane >> 2);
    int crB = crA + 8;
    int gcA = c0 + crA, gcB = c0 + crB;
    float biasA = sBias[crA], biasB = sBias[crB];
    #pragma unroll
    for (int nt = 0; nt < 4; ++nt) {
        int bcol = b0 + nt * 8 + 2 * (lane & 3);
        if (gcA < NCLS) {
            out[(long)bcol * NCLS + gcA]       = acc[nt][0] + biasA;
            out[(long)(bcol + 1) * NCLS + gcA] = acc[nt][1] + biasA;
        }
        if (gcB < NCLS) {
            out[(long)bcol * NCLS + gcB]       = acc[nt][2] + biasB;
            out[(long)(bcol + 1) * NCLS + gcB] = acc[nt][3] + biasB;
        }
    }
}

// ---------------- launcher ----------------
extern "C" void kernel_launch(void* const* d_in, const int* in_sizes, int n_in,
                              void* d_out, int out_size) {
    const int*   ltext  = (const int*)d_in[0];
    const int*   gtext  = (const int*)d_in[1];
    const float* emb    = (const float*)d_in[2];
    const float* att_w  = (const float*)d_in[3];
    const float* att_b  = (const float*)d_in[4];
    const float* att2_w = (const float*)d_in[5];
    const float* att2_b = (const float*)d_in[6];
    const float* c1w    = (const float*)d_in[7];
    const float* c1b    = (const float*)d_in[8];
    const float* c2w    = (const float*)d_in[9];
    const float* c2b    = (const float*)d_in[10];
    const float* c3w    = (const float*)d_in[11];
    const float* c3b    = (const float*)d_in[12];
    const float* mfw    = (const float*)d_in[13];
    const float* mfb    = (const float*)d_in[14];
    const float* finw   = (const float*)d_in[15];
    const float* finb   = (const float*)d_in[16];
    const float* f2w    = (const float*)d_in[17];
    const float* f2b    = (const float*)d_in[18];
    float* out = (float*)d_out;

    k_zero<<<300, 256>>>();
    k_wprep<<<(21 * 832 + 255) / 256, 256>>>(c1w, c2w, c3w);
    k_w2prep<<<(3072 * 200 + 255) / 256, 256>>>(f2w);
    k_token<<<(BB * TOKP + 3) / 4, 128>>>(ltext, emb, att_w, att_b);
    k_conv_mma<<<dim3(5, BB), 192>>>(gtext, emb, c1b, c2b, c3b);
    k_cmp<<<SCAN_KEEP, 256>>>();
    k_tail<<<BB, 512>>>(ltext, emb, att2_w, att2_b, mfw, mfb, finw, finb);
    k_out_mma<<<dim3(32, 8), 192>>>(f2b, out);
}

// round 16
// speedup vs baseline: 2.6551x; 1.0765x over previous
#include <cuda_runtime.h>
#include <math.h>
#include <stdint.h>

#define BB   256
#define DM   100
#define LLEN 415
#define LGG  411
#define PP   411
#define NF   100
#define NCLS 2987

#define QSCALE 12700.0f
#define QINV   (1.0f / (12700.0f * 12700.0f))

// ---------------- scratch (device globals; no allocation) ----------------
__device__ float    d_Asum[BB * LLEN];
__device__ float    d_Tsum[BB * LLEN];
__device__ float    d_cmp[PP];
__device__ unsigned d_pooled[BB * 300];
__device__ float    d_combine[BB * 200];
__device__ __align__(16) uint32_t d_wq[21 * 832];       // s8 conv W slices
__device__ __align__(16) uint32_t d_hbf[25 * 32 * 64];  // hidden bf16x2 B-frag layout
__device__ __align__(16) uint32_t d_w2bf[3072 * 200];   // fin2_w bf16x2 A-frag rows

// packed f32x2 FMA
__device__ __forceinline__ unsigned long long ffma2(unsigned long long a,
                                                    unsigned long long b,
                                                    unsigned long long c) {
    unsigned long long d;
    asm("fma.rn.f32x2 %0, %1, %2, %3;" : "=l"(d) : "l"(a), "l"(b), "l"(c));
    return d;
}
__device__ __forceinline__ float acc2_sum(unsigned long long a) {
    return __uint_as_float((unsigned)(a & 0xffffffffull)) +
           __uint_as_float((unsigned)(a >> 32));
}
__device__ __forceinline__ uint32_t pack_bf16(float lo, float hi) {
    uint32_t r;
    asm("cvt.rn.bf16x2.f32 %0, %1, %2;" : "=r"(r) : "f"(hi), "f"(lo));
    return r;
}
__device__ __forceinline__ uint32_t packq4(float v0, float v1, float v2, float v3) {
    int q0 = __float2int_rn(v0 * QSCALE) & 255;
    int q1 = __float2int_rn(v1 * QSCALE) & 255;
    int q2 = __float2int_rn(v2 * QSCALE) & 255;
    int q3 = __float2int_rn(v3 * QSCALE) & 255;
    return (uint32_t)(q0 | (q1 << 8) | (q2 << 16) | (q3 << 24));
}
__device__ __forceinline__ void mma16n8k32s8(int* c, uint32_t a0, uint32_t a1,
                                             uint32_t a2, uint32_t a3,
                                             uint32_t b0, uint32_t b1) {
    asm volatile(
        "mma.sync.aligned.m16n8k32.row.col.s32.s8.s8.s32 "
        "{%0,%1,%2,%3}, {%4,%5,%6,%7}, {%8,%9}, {%0,%1,%2,%3};"
        : "+r"(c[0]), "+r"(c[1]), "+r"(c[2]), "+r"(c[3])
        : "r"(a0), "r"(a1), "r"(a2), "r"(a3), "r"(b0), "r"(b1));
}
__device__ __forceinline__ void mma16n8k16bf(float* c, uint32_t a0, uint32_t a1,
                                             uint32_t a2, uint32_t a3,
                                             uint32_t b0, uint32_t b1) {
    asm volatile(
        "mma.sync.aligned.m16n8k16.row.col.f32.bf16.bf16.f32 "
        "{%0,%1,%2,%3}, {%4,%5,%6,%7}, {%8,%9}, {%0,%1,%2,%3};"
        : "+f"(c[0]), "+f"(c[1]), "+f"(c[2]), "+f"(c[3])
        : "r"(a0), "r"(a1), "r"(a2), "r"(a3), "r"(b0), "r"(b1));
}
__device__ __forceinline__ uint32_t smem_u32p(const void* p) {
    return (uint32_t)__cvta_generic_to_shared(p);
}
__device__ __forceinline__ void cp_async16(uint32_t saddr, const void* g) {
    asm volatile("cp.async.cg.shared.global [%0], [%1], 16;"
                 :: "r"(saddr), "l"(g) : "memory");
}
__device__ __forceinline__ void cp_commit() {
    asm volatile("cp.async.commit_group;" ::: "memory");
}
template <int N>
__device__ __forceinline__ void cp_wait() {
    asm volatile("cp.async.wait_group %0;" :: "n"(N) : "memory");
}

#define SCAN_KEEP 64
#define SCAN_START (PP - SCAN_KEEP)   // 347
#define TOKP (SCAN_KEEP + 4)          // 68 positions: 347..414

// ---------------- K0: fused prep (zero pooled + conv W s8 + fin2_w bf16) ----
#define PREP_ZERO (BB * 300)            // 76800
#define PREP_WQ   (21 * 832)            // 17472
#define PREP_W2   (3072 * 200)          // 614400
#define PREP_TOT  (PREP_ZERO + PREP_WQ + PREP_W2)
__global__ void k_prep(const float* __restrict__ w1, const float* __restrict__ w2,
                       const float* __restrict__ w3, const float* __restrict__ fw) {
    int idx = blockIdx.x * blockDim.x + threadIdx.x;
    if (idx < PREP_ZERO) {
        d_pooled[idx] = 0u;
    } else if (idx < PREP_ZERO + PREP_WQ) {
        int i = idx - PREP_ZERO;
        int q = i / 832, r = i - q * 832;
        int g = (q < 4) ? 0 : (q < 11) ? 1 : 2;
        int chunk = q - ((g == 0) ? 0 : (g == 1) ? 4 : 11);
        int Kg = (g + 1) * 100;
        const float* w = (g == 0) ? w1 : (g == 1) ? w2 : w3;
        int nt = r >> 6, rem = r & 63, fp = rem >> 3, pos = rem & 7;
        int kg = (pos & 1) ? (pos >> 1) + 4 : (pos >> 1);
        int flat = chunk * 32 + kg * 4;
        int f = nt * 8 + fp;
        float v[4];
        #pragma unroll
        for (int j = 0; j < 4; ++j) {
            int fl = flat + j;
            v[j] = (f < 100 && fl < Kg) ? w[f * Kg + fl] : 0.f;
        }
        d_wq[i] = packq4(v[0], v[1], v[2], v[3]);
    } else if (idx < PREP_TOT) {
        int i = idx - PREP_ZERO - PREP_WQ;
        int cc = i / 200, q = i - cc * 200;
        float v0 = 0.f, v1 = 0.f;
        if (cc < NCLS) {
            v0 = fw[(long)cc * 400 + 2 * q];
            v1 = fw[(long)cc * 400 + 2 * q + 1];
        }
        int bq = q & 7;
        int p = (bq < 4) ? 2 * bq : 2 * (bq - 4) + 1;
        d_w2bf[cc * 200 + (q & ~7) + p] = pack_bf16(v0, v1);
    }
}

// ---------------- K1: per-token Asum + row-sum, float4 loads ----------------
__global__ void k_token(const int* __restrict__ ltext, const float* __restrict__ emb,
                        const float* __restrict__ att_w, const float* __restrict__ att_b) {
    int warp = (blockIdx.x * blockDim.x + threadIdx.x) >> 5;
    int lane = threadIdx.x & 31;
    if (warp >= BB * TOKP) return;
    int b = warp / TOKP;
    int pos = SCAN_START + (warp - b * TOKP);
    int tok = ltext[b * LLEN + pos];
    float s[5] = {0.f, 0.f, 0.f, 0.f, 0.f};
    float ts = 0.f;
    if (lane < 25) {
        float4 e = *reinterpret_cast<const float4*>(emb + (long)tok * DM + lane * 4);
        ts = e.x + e.y + e.z + e.w;
        #pragma unroll
        for (int w = 0; w < 5; ++w) {
            float4 a = *reinterpret_cast<const float4*>(att_w + w * DM + lane * 4);
            s[w] = e.x * a.x + e.y * a.y + e.z * a.z + e.w * a.w;
        }
    }
    #pragma unroll
    for (int o = 16; o > 0; o >>= 1) {
        #pragma unroll
        for (int w = 0; w < 5; ++w) s[w] += __shfl_xor_sync(0xffffffffu, s[w], o);
        ts += __shfl_xor_sync(0xffffffffu, ts, o);
    }
    if (lane == 0) {
        float a = 0.f;
        #pragma unroll
        for (int w = 0; w < 5; ++w) a += tanhf(s[w] + att_b[w]);
        d_Asum[b * LLEN + pos] = a;
        d_Tsum[b * LLEN + pos] = ts;
    }
}

// ---------------- K2: comparison[p], p in 347..410 only ----------------
__global__ void k_cmp() {
    __shared__ float smn[256], smx[256];
    int p = SCAN_START + blockIdx.x;
    int b = threadIdx.x;
    const float* a = d_Asum + b * LLEN + p;
    float mn = a[0], mx = a[0];
    #pragma unroll
    for (int w = 1; w < 5; ++w) { float v = a[w]; mn = fminf(mn, v); mx = fmaxf(mx, v); }
    smn[b] = mn; smx[b] = mx;
    __syncthreads();
    for (int sft = 128; sft > 0; sft >>= 1) {
        if (b < sft) {
            smn[b] = fminf(smn[b], smn[b + sft]);
            smx[b] = fmaxf(smx[b], smx[b + sft]);
        }
        __syncthreads();
    }
    if (b == 0) d_cmp[p] = 0.8f * smn[0] + 0.8f * smx[0];
}

// ---------------- K5: conv via mma.sync s8 (m16n8k32), shift folded into K --
#define EPQ 36
#define NBUF 4
__global__ void __launch_bounds__(192, 4) k_conv_mma(
    const int* __restrict__ gtext, const float* __restrict__ emb,
    const float* __restrict__ cb1, const float* __restrict__ cb2,
    const float* __restrict__ cb3) {
    __shared__ __align__(16) uint32_t EgS[98 * EPQ];    // 14112 B
    __shared__ __align__(16) uint32_t Bs[NBUF][832];    // 13312 B
    __shared__ float sBias[3][104];
    __shared__ int   sToks[98];
    int tid = threadIdx.x, lane = tid & 31, wid = tid >> 5;
    int t0 = blockIdx.x * 96, b = blockIdx.y;

    const float* cbs[3] = {cb1, cb2, cb3};
    for (int u = tid; u < 312; u += 192) {
        int g = u / 104, f = u - g * 104;
        sBias[g][f] = (f < 100) ? cbs[g][f] : 0.f;
    }
    if (tid < 98) {
        int gt = t0 + tid;
        sToks[tid] = (gt < LGG) ? gtext[b * LGG + gt] : -1;
    }
    __syncthreads();
    for (int u = tid; u < 98 * 25; u += 192) {
        int r = u / 25, kg = u - r * 25;
        int tok = sToks[r];
        uint32_t packed = 0;
        if (tok >= 0) {
            float4 f = *reinterpret_cast<const float4*>(emb + (long)tok * DM + kg * 4);
            packed = packq4(f.x, f.y, f.z, f.w);
        }
        EgS[r * EPQ + kg] = packed;
    }

    uint32_t bs_base[NBUF];
    #pragma unroll
    for (int j = 0; j < NBUF; ++j) bs_base[j] = smem_u32p(&Bs[j][0]);
    int chunk = tid;
    #pragma unroll
    for (int j = 0; j < 3; ++j) {
        if (chunk < 208) cp_async16(bs_base[j] + chunk * 16, &d_wq[j * 832 + chunk * 4]);
        if (tid < 16)    cp_async16(bs_base[j] + (192 + tid) * 16,
                                    &d_wq[j * 832 + (192 + tid) * 4]);
        cp_commit();
    }

    int rowbase = (wid * 16 + (lane >> 2)) * EPQ;
    int cb4 = (lane & 3) << 2;
    const int nsArr[3] = {4, 7, 10};

    int q = 0;
    for (int g = 0; g < 3; ++g) {
        int acc[13][4];
        #pragma unroll
        for (int nt = 0; nt < 13; ++nt)
            #pragma unroll
            for (int j = 0; j < 4; ++j) acc[nt][j] = 0;
        int ns = nsArr[g];
        for (int i = 0; i < ns; ++i, ++q) {
            cp_wait<2>();
            __syncthreads();
            {
                int jn = q + 3;
                if (jn < 21) {
                    uint32_t sb = bs_base[jn & 3];
                    const uint32_t* gp = &d_wq[jn * 832];
                    cp_async16(sb + chunk * 16, gp + chunk * 4);
                    if (tid < 16) cp_async16(sb + (192 + tid) * 16, gp + (192 + tid) * 4);
                }
                cp_commit();
            }
            const uint32_t* Bcur = &Bs[q & 3][0];
            int flat0 = (i << 5) + cb4;
            int flat1 = flat0 + 16;
            int s0 = (flat0 >= 100) + (flat0 >= 200);
            int s1 = (flat1 >= 100) + (flat1 >= 200);
            int idx0 = (flat0 >> 2) + s0 * (EPQ - 25);
            int idx1 = (flat1 >> 2) + s1 * (EPQ - 25);
            uint32_t a0 = EgS[rowbase + idx0];
            uint32_t a1 = EgS[rowbase + 8 * EPQ + idx0];
            uint32_t a2 = EgS[rowbase + idx1];
            uint32_t a3 = EgS[rowbase + 8 * EPQ + idx1];
            const uint32_t* bp = Bcur + (lane >> 2) * 8 + 2 * (lane & 3);
            #pragma unroll
            for (int nt = 0; nt < 13; ++nt) {
                uint2 bv = *reinterpret_cast<const uint2*>(bp + nt * 64);
                mma16n8k32s8(acc[nt], a0, a1, a2, a3, bv.x, bv.y);
            }
        }
        int Ts = LGG - g;
        int tA = t0 + wid * 16 + (lane >> 2);
        int tB = tA + 8;
        unsigned* pool = d_pooled + b * 300 + g * 100;
        #pragma unroll
        for (int nt = 0; nt < 13; ++nt) {
            float v0 = (tA < Ts) ? (float)acc[nt][0] * QINV : -1e30f;
            float v1 = (tA < Ts) ? (float)acc[nt][1] * QINV : -1e30f;
            float v2 = (tB < Ts) ? (float)acc[nt][2] * QINV : -1e30f;
            float v3 = (tB < Ts) ? (float)acc[nt][3] * QINV : -1e30f;
            v0 = fmaxf(v0, v2);
            v1 = fmaxf(v1, v3);
            #pragma unroll
            for (int off = 16; off >= 4; off >>= 1) {
                v0 = fmaxf(v0, __shfl_xor_sync(0xffffffffu, v0, off));
                v1 = fmaxf(v1, __shfl_xor_sync(0xffffffffu, v1, off));
            }
            if (lane < 4) {
                int f0 = nt * 8 + lane * 2;
                float r0v = fmaxf(v0 + sBias[g][f0], 0.f);
                float r1v = fmaxf(v1 + sBias[g][f0 + 1], 0.f);
                if (f0 < 100)     atomicMax(&pool[f0],     __float_as_uint(r0v));
                if (f0 + 1 < 100) atomicMax(&pool[f0 + 1], __float_as_uint(r1v));
            }
        }
    }
}

// ---------------- K6: fused scan + local + global -> d_combine -------------
__global__ void __launch_bounds__(256) k_tail(
    const int* __restrict__ ltext, const float* __restrict__ emb,
    const float* __restrict__ att2_w, const float* __restrict__ att2_b,
    const float* __restrict__ mf_w, const float* __restrict__ mf_b) {
    __shared__ int   toks[SCAN_KEEP];
    __shared__ float jflag[SCAN_KEEP];
    __shared__ float twr[DM];
    __shared__ float combine[200];
    __shared__ float ps[300];
    int b = blockIdx.x, tid = threadIdx.x;

    if (tid < SCAN_KEEP) {
        int p = SCAN_START + tid;
        toks[tid]  = ltext[b * LLEN + p + 2];
        jflag[tid] = (d_Tsum[b * LLEN + p + 2] > d_cmp[p]) ? 1.f : 0.f;
    }
    for (int u = tid; u < 300; u += 256)
        ps[u] = __uint_as_float(d_pooled[b * 300 + u]);
    __syncthreads();

    if (tid < DM) {                     // scan -> tw (fp32-exact truncation)
        const float r = 1.0f / 411.0f;
        float tw = 0.f;
        #pragma unroll 8
        for (int i = 0; i < SCAN_KEEP; ++i) {
            float e = emb[(long)toks[i] * DM + tid] * jflag[i];
            tw = (tw + e) * r;
        }
        twr[tid] = tw;
    } else if (tid >= 128 && tid < 228) {  // global_units
        int f = tid - 128;
        float acc = mf_b[f];
        const float* wr = mf_w + f * 300;
        #pragma unroll 4
        for (int i = 0; i < 300; ++i) acc += ps[i] * wr[i];
        combine[100 + f] = acc;
    }
    __syncthreads();

    if (tid < DM) {                     // local_units
        float acc = att2_b[tid];
        const float* wr = att2_w + tid * DM;
        #pragma unroll 4
        for (int d = 0; d < DM; ++d) acc += twr[d] * wr[d];
        combine[tid] = acc;
    }
    __syncthreads();

    if (tid < 200) d_combine[b * 200 + tid] = combine[tid];
}

// ---------------- K7: fin GEMM: hidden = relu(combine @ fin_w.T + b) -------
// 128 c x 64 b tile, fp32 ffma2, combine chunks staged in smem. Packs bf16
// hidden directly into d_hbf (even-lane shfl pairing). Grid 4 x 4.
__global__ void __launch_bounds__(512) k_fin(const float* __restrict__ fw,
                                             const float* __restrict__ fb) {
    __shared__ float cs[64 * 100];
    int c0 = blockIdx.x * 128;
    int b0 = blockIdx.y * 64;
    int tid = threadIdx.x;
    int ci = tid & 127, bg = tid >> 7;
    int c = c0 + ci;
    bool cvalid = (c < 400);

    unsigned long long acc[16];
    #pragma unroll
    for (int i = 0; i < 16; ++i) acc[i] = 0ull;

    for (int p = 0; p < 2; ++p) {
        __syncthreads();
        for (int u = tid; u < 64 * 100; u += 512)
            cs[u] = d_combine[(b0 + u / 100) * 200 + p * 100 + (u % 100)];
        __syncthreads();
        if (cvalid) {
            const float* wr = fw + (long)c * 200 + p * 100;
            const float* hb = cs + bg * 16 * 100;
            for (int h = 0; h < 100; h += 2) {
                unsigned long long wv = *reinterpret_cast<const unsigned long long*>(wr + h);
                #pragma unroll
                for (int i = 0; i < 16; ++i) {
                    unsigned long long hv =
                        *reinterpret_cast<const unsigned long long*>(hb + i * 100 + h);
                    acc[i] = ffma2(wv, hv, acc[i]);
                }
            }
        }
    }
    float bias = cvalid ? fb[c] : 0.f;
    int chunkc = c >> 4;                 // hidden k-chunk for d_hbf
    int p2 = ((c >> 1) & 7);
    p2 = (p2 < 4) ? 2 * p2 : 2 * (p2 - 4) + 1;
    #pragma unroll
    for (int i = 0; i < 16; ++i) {
        float hid = cvalid ? fmaxf(acc2_sum(acc[i]) + bias, 0.f) : 0.f;
        float hiv = __shfl_down_sync(0xffffffffu, hid, 1);
        if (cvalid && !(ci & 1)) {
            int bb = b0 + bg * 16 + i;
            d_hbf[((chunkc * 32 + (bb >> 3)) * 8 + (bb & 7)) * 8 + p2] =
                pack_bf16(hid, hiv);
        }
    }
}

// ---------------- K8: out = hidden @ fin2_w.T + b via bf16 MMA -------------
__global__ void __launch_bounds__(192) k_out_mma(const float* __restrict__ fb,
                                                 float* __restrict__ out) {
    __shared__ __align__(16) uint32_t sB[25 * 4 * 64];   // 25600 B
    __shared__ float sBias[96];
    int tid = threadIdx.x, lane = tid & 31, wid = tid >> 5;
    int c0 = blockIdx.x * 96;
    int b0 = blockIdx.y * 32;
    int bt0 = blockIdx.y * 4;

    if (tid < 96) {
        int c = c0 + tid;
        sBias[tid] = (c < NCLS) ? fb[c] : 0.f;
    }
    {
        uint32_t sbase = smem_u32p(sB);
        for (int i = tid; i < 1600; i += 192) {
            int c = i >> 6, rem = i & 63, btl = rem >> 4, j = rem & 15;
            cp_async16(sbase + (uint32_t)(((c * 4 + btl) * 64 + j * 4) * 4),
                       &d_hbf[(c * 32 + bt0 + btl) * 64 + j * 4]);
        }
        cp_commit();
    }
    cp_wait<0>();
    __syncthreads();

    float acc[4][4];
    #pragma unroll
    for (int nt = 0; nt < 4; ++nt)
        #pragma unroll
        for (int j = 0; j < 4; ++j) acc[nt][j] = 0.f;

    const uint32_t* arow = &d_w2bf[(long)(c0 + wid * 16 + (lane >> 2)) * 200
                                   + 2 * (lane & 3)];
    const uint32_t* bp = &sB[(lane >> 2) * 8 + 2 * (lane & 3)];

    uint2 pLo = *reinterpret_cast<const uint2*>(arow);
    uint2 pHi = *reinterpret_cast<const uint2*>(arow + 8 * 200);
    for (int c = 0; c < 25; ++c) {
        uint2 aLo = pLo, aHi = pHi;
        if (c + 1 < 25) {
            pLo = *reinterpret_cast<const uint2*>(arow + (c + 1) * 8);
            pHi = *reinterpret_cast<const uint2*>(arow + 8 * 200 + (c + 1) * 8);
        }
        const uint32_t* bc = bp + c * 256;
        #pragma unroll
        for (int nt = 0; nt < 4; ++nt) {
            uint2 bv = *reinterpret_cast<const uint2*>(bc + nt * 64);
            mma16n8k16bf(acc[nt], aLo.x, aHi.x, aLo.y, aHi.y, bv.x, bv.y);
        }
    }
    int crA = wid * 16 + (lane >> 2);
    int crB = crA + 8;
    int gcA = c0 + crA, gcB = c0 + crB;
    float biasA = sBias[crA], biasB = sBias[crB];
    #pragma unroll
    for (int nt = 0; nt < 4; ++nt) {
        int bcol = b0 + nt * 8 + 2 * (lane & 3);
        if (gcA < NCLS) {
            out[(long)bcol * NCLS + gcA]       = acc[nt][0] + biasA;
            out[(long)(bcol + 1) * NCLS + gcA] = acc[nt][1] + biasA;
        }
        if (gcB < NCLS) {
            out[(long)bcol * NCLS + gcB]       = acc[nt][2] + biasB;
            out[(long)(bcol + 1) * NCLS + gcB] = acc[nt][3] + biasB;
        }
    }
}

// ---------------- launcher ----------------
extern "C" void kernel_launch(void* const* d_in, const int* in_sizes, int n_in,
                              void* d_out, int out_size) {
    const int*   ltext  = (const int*)d_in[0];
    const int*   gtext  = (const int*)d_in[1];
    const float* emb    = (const float*)d_in[2];
    const float* att_w  = (const float*)d_in[3];
    const float* att_b  = (const float*)d_in[4];
    const float* att2_w = (const float*)d_in[5];
    const float* att2_b = (const float*)d_in[6];
    const float* c1w    = (const float*)d_in[7];
    const float* c1b    = (const float*)d_in[8];
    const float* c2w    = (const float*)d_in[9];
    const float* c2b    = (const float*)d_in[10];
    const float* c3w    = (const float*)d_in[11];
    const float* c3b    = (const float*)d_in[12];
    const float* mfw    = (const float*)d_in[13];
    const float* mfb    = (const float*)d_in[14];
    const float* finw   = (const float*)d_in[15];
    const float* finb   = (const float*)d_in[16];
    const float* f2w    = (const float*)d_in[17];
    const float* f2b    = (const float*)d_in[18];
    float* out = (float*)d_out;

    k_prep<<<(PREP_TOT + 255) / 256, 256>>>(c1w, c2w, c3w, f2w);
    k_token<<<(BB * TOKP + 3) / 4, 128>>>(ltext, emb, att_w, att_b);
    k_cmp<<<SCAN_KEEP, 256>>>();
    k_conv_mma<<<dim3(5, BB), 192>>>(gtext, emb, c1b, c2b, c3b);
    k_tail<<<BB, 256>>>(ltext, emb, att2_w, att2_b, mfw, mfb);
    k_fin<<<dim3(4, 4), 512>>>(finw, finb);
    k_out_mma<<<dim3(32, 8), 192>>>(f2b, out);
}

// round 17
// speedup vs baseline: 2.9504x; 1.1112x over previous
#include <cuda_runtime.h>
#include <math.h>
#include <stdint.h>

#define BB   256
#define DM   100
#define LLEN 415
#define LGG  411
#define PP   411
#define NF   100
#define NCLS 2987

#define QSCALE 12700.0f
#define QINV   (1.0f / (12700.0f * 12700.0f))

// ---------------- scratch (device globals; no allocation) ----------------
__device__ float    d_Asum[BB * LLEN];
__device__ float    d_Tsum[BB * LLEN];
__device__ float    d_cmp[PP];
__device__ unsigned d_pooled[BB * 300];
__device__ float    d_combine[BB * 200];
__device__ __align__(16) uint32_t d_wq[21 * 832];       // s8 conv W slices
__device__ __align__(16) uint32_t d_hbf[25 * 32 * 64];  // hidden bf16x2 B-frag layout
__device__ __align__(16) uint32_t d_w2bf[3072 * 200];   // fin2_w bf16x2 A-frag rows

// packed f32x2 FMA
__device__ __forceinline__ unsigned long long ffma2(unsigned long long a,
                                                    unsigned long long b,
                                                    unsigned long long c) {
    unsigned long long d;
    asm("fma.rn.f32x2 %0, %1, %2, %3;" : "=l"(d) : "l"(a), "l"(b), "l"(c));
    return d;
}
__device__ __forceinline__ float acc2_sum(unsigned long long a) {
    return __uint_as_float((unsigned)(a & 0xffffffffull)) +
           __uint_as_float((unsigned)(a >> 32));
}
__device__ __forceinline__ uint32_t pack_bf16(float lo, float hi) {
    uint32_t r;
    asm("cvt.rn.bf16x2.f32 %0, %1, %2;" : "=r"(r) : "f"(hi), "f"(lo));
    return r;
}
__device__ __forceinline__ uint32_t packq4(float v0, float v1, float v2, float v3) {
    int q0 = __float2int_rn(v0 * QSCALE) & 255;
    int q1 = __float2int_rn(v1 * QSCALE) & 255;
    int q2 = __float2int_rn(v2 * QSCALE) & 255;
    int q3 = __float2int_rn(v3 * QSCALE) & 255;
    return (uint32_t)(q0 | (q1 << 8) | (q2 << 16) | (q3 << 24));
}
__device__ __forceinline__ void mma16n8k32s8(int* c, uint32_t a0, uint32_t a1,
                                             uint32_t a2, uint32_t a3,
                                             uint32_t b0, uint32_t b1) {
    asm volatile(
        "mma.sync.aligned.m16n8k32.row.col.s32.s8.s8.s32 "
        "{%0,%1,%2,%3}, {%4,%5,%6,%7}, {%8,%9}, {%0,%1,%2,%3};"
        : "+r"(c[0]), "+r"(c[1]), "+r"(c[2]), "+r"(c[3])
        : "r"(a0), "r"(a1), "r"(a2), "r"(a3), "r"(b0), "r"(b1));
}
__device__ __forceinline__ void mma16n8k16bf(float* c, uint32_t a0, uint32_t a1,
                                             uint32_t a2, uint32_t a3,
                                             uint32_t b0, uint32_t b1) {
    asm volatile(
        "mma.sync.aligned.m16n8k16.row.col.f32.bf16.bf16.f32 "
        "{%0,%1,%2,%3}, {%4,%5,%6,%7}, {%8,%9}, {%0,%1,%2,%3};"
        : "+f"(c[0]), "+f"(c[1]), "+f"(c[2]), "+f"(c[3])
        : "r"(a0), "r"(a1), "r"(a2), "r"(a3), "r"(b0), "r"(b1));
}
__device__ __forceinline__ uint32_t smem_u32p(const void* p) {
    return (uint32_t)__cvta_generic_to_shared(p);
}
__device__ __forceinline__ void cp_async16(uint32_t saddr, const void* g) {
    asm volatile("cp.async.cg.shared.global [%0], [%1], 16;"
                 :: "r"(saddr), "l"(g) : "memory");
}
__device__ __forceinline__ void cp_commit() {
    asm volatile("cp.async.commit_group;" ::: "memory");
}
template <int N>
__device__ __forceinline__ void cp_wait() {
    asm volatile("cp.async.wait_group %0;" :: "n"(N) : "memory");
}

#define SCAN_KEEP 64
#define SCAN_START (PP - SCAN_KEEP)   // 347
#define TOKP (SCAN_KEEP + 4)          // 68 positions: 347..414

// ---------------- K0: fused prep + per-token attention ---------------------
#define PREP_ZERO (BB * 300)            // 76800
#define PREP_WQ   (21 * 832)            // 17472
#define PREP_W2   (3072 * 200)          // 614400
#define PREP_TOT  (PREP_ZERO + PREP_WQ + PREP_W2)
#define PREP_BLKS ((PREP_TOT + 255) / 256)          // 2770
#define TOK_BLKS  ((BB * TOKP + 7) / 8)             // 2176 (8 warps/block)
__global__ void k_prep(const float* __restrict__ w1, const float* __restrict__ w2,
                       const float* __restrict__ w3, const float* __restrict__ fw,
                       const int* __restrict__ ltext, const float* __restrict__ emb,
                       const float* __restrict__ att_w, const float* __restrict__ att_b) {
    if (blockIdx.x < PREP_BLKS) {
        int idx = blockIdx.x * 256 + threadIdx.x;
        if (idx < PREP_ZERO) {
            d_pooled[idx] = 0u;
        } else if (idx < PREP_ZERO + PREP_WQ) {
            int i = idx - PREP_ZERO;
            int q = i / 832, r = i - q * 832;
            int g = (q < 4) ? 0 : (q < 11) ? 1 : 2;
            int chunk = q - ((g == 0) ? 0 : (g == 1) ? 4 : 11);
            int Kg = (g + 1) * 100;
            const float* w = (g == 0) ? w1 : (g == 1) ? w2 : w3;
            int nt = r >> 6, rem = r & 63, fp = rem >> 3, pos = rem & 7;
            int kg = (pos & 1) ? (pos >> 1) + 4 : (pos >> 1);
            int flat = chunk * 32 + kg * 4;
            int f = nt * 8 + fp;
            float v[4];
            #pragma unroll
            for (int j = 0; j < 4; ++j) {
                int fl = flat + j;
                v[j] = (f < 100 && fl < Kg) ? w[f * Kg + fl] : 0.f;
            }
            d_wq[i] = packq4(v[0], v[1], v[2], v[3]);
        } else if (idx < PREP_TOT) {
            int i = idx - PREP_ZERO - PREP_WQ;
            int cc = i / 200, q = i - cc * 200;
            float v0 = 0.f, v1 = 0.f;
            if (cc < NCLS) {
                v0 = fw[(long)cc * 400 + 2 * q];
                v1 = fw[(long)cc * 400 + 2 * q + 1];
            }
            int bq = q & 7;
            int p = (bq < 4) ? 2 * bq : 2 * (bq - 4) + 1;
            d_w2bf[cc * 200 + (q & ~7) + p] = pack_bf16(v0, v1);
        }
        return;
    }
    // ---- token part ----
    int warp = (blockIdx.x - PREP_BLKS) * 8 + (threadIdx.x >> 5);
    int lane = threadIdx.x & 31;
    if (warp >= BB * TOKP) return;
    int b = warp / TOKP;
    int pos = SCAN_START + (warp - b * TOKP);
    int tok = ltext[b * LLEN + pos];
    float s[5] = {0.f, 0.f, 0.f, 0.f, 0.f};
    float ts = 0.f;
    if (lane < 25) {
        float4 e = *reinterpret_cast<const float4*>(emb + (long)tok * DM + lane * 4);
        ts = e.x + e.y + e.z + e.w;
        #pragma unroll
        for (int w = 0; w < 5; ++w) {
            float4 a = *reinterpret_cast<const float4*>(att_w + w * DM + lane * 4);
            s[w] = e.x * a.x + e.y * a.y + e.z * a.z + e.w * a.w;
        }
    }
    #pragma unroll
    for (int o = 16; o > 0; o >>= 1) {
        #pragma unroll
        for (int w = 0; w < 5; ++w) s[w] += __shfl_xor_sync(0xffffffffu, s[w], o);
        ts += __shfl_xor_sync(0xffffffffu, ts, o);
    }
    if (lane == 0) {
        float a = 0.f;
        #pragma unroll
        for (int w = 0; w < 5; ++w) a += tanhf(s[w] + att_b[w]);
        d_Asum[b * LLEN + pos] = a;
        d_Tsum[b * LLEN + pos] = ts;
    }
}

// ---------------- K2: comparison[p], p in 347..410 only ----------------
__global__ void k_cmp() {
    __shared__ float smn[256], smx[256];
    int p = SCAN_START + blockIdx.x;
    int b = threadIdx.x;
    const float* a = d_Asum + b * LLEN + p;
    float mn = a[0], mx = a[0];
    #pragma unroll
    for (int w = 1; w < 5; ++w) { float v = a[w]; mn = fminf(mn, v); mx = fmaxf(mx, v); }
    smn[b] = mn; smx[b] = mx;
    __syncthreads();
    for (int sft = 128; sft > 0; sft >>= 1) {
        if (b < sft) {
            smn[b] = fminf(smn[b], smn[b + sft]);
            smx[b] = fmaxf(smx[b], smx[b + sft]);
        }
        __syncthreads();
    }
    if (b == 0) d_cmp[p] = 0.8f * smn[0] + 0.8f * smx[0];
}

// ---------------- K5: conv s8 MMA; 7 warps, t-tile 112, grid (4, BB) -------
#define EPQ 36
#define NBUF 4
#define TT7 112
__global__ void __launch_bounds__(224, 3) k_conv_mma(
    const int* __restrict__ gtext, const float* __restrict__ emb,
    const float* __restrict__ cb1, const float* __restrict__ cb2,
    const float* __restrict__ cb3) {
    __shared__ __align__(16) uint32_t EgS[114 * EPQ];   // 16416 B
    __shared__ __align__(16) uint32_t Bs[NBUF][832];    // 13312 B
    __shared__ float sBias[3][104];
    __shared__ int   sToks[114];
    int tid = threadIdx.x, lane = tid & 31, wid = tid >> 5;
    int t0 = blockIdx.x * TT7, b = blockIdx.y;

    const float* cbs[3] = {cb1, cb2, cb3};
    for (int u = tid; u < 312; u += 224) {
        int g = u / 104, f = u - g * 104;
        sBias[g][f] = (f < 100) ? cbs[g][f] : 0.f;
    }
    if (tid < 114) {
        int gt = t0 + tid;
        sToks[tid] = (gt < LGG) ? gtext[b * LGG + gt] : -1;
    }
    __syncthreads();
    for (int u = tid; u < 114 * 25; u += 224) {
        int r = u / 25, kg = u - r * 25;
        int tok = sToks[r];
        uint32_t packed = 0;
        if (tok >= 0) {
            float4 f = *reinterpret_cast<const float4*>(emb + (long)tok * DM + kg * 4);
            packed = packq4(f.x, f.y, f.z, f.w);
        }
        EgS[r * EPQ + kg] = packed;
    }

    uint32_t bs_base[NBUF];
    #pragma unroll
    for (int j = 0; j < NBUF; ++j) bs_base[j] = smem_u32p(&Bs[j][0]);
    #pragma unroll
    for (int j = 0; j < 3; ++j) {                       // prologue: slices 0..2
        if (tid < 208) cp_async16(bs_base[j] + tid * 16, &d_wq[j * 832 + tid * 4]);
        cp_commit();
    }

    int rowbase = (wid * 16 + (lane >> 2)) * EPQ;
    int cb4 = (lane & 3) << 2;
    const int nsArr[3] = {4, 7, 10};

    int q = 0;
    for (int g = 0; g < 3; ++g) {
        int acc[13][4];
        #pragma unroll
        for (int nt = 0; nt < 13; ++nt)
            #pragma unroll
            for (int j = 0; j < 4; ++j) acc[nt][j] = 0;
        int ns = nsArr[g];
        for (int i = 0; i < ns; ++i, ++q) {
            cp_wait<2>();
            __syncthreads();
            {
                int jn = q + 3;
                if (jn < 21) {
                    if (tid < 208)
                        cp_async16(bs_base[jn & 3] + tid * 16, &d_wq[jn * 832 + tid * 4]);
                }
                cp_commit();
            }
            const uint32_t* Bcur = &Bs[q & 3][0];
            int flat0 = (i << 5) + cb4;
            int flat1 = flat0 + 16;
            int s0 = (flat0 >= 100) + (flat0 >= 200);
            int s1 = (flat1 >= 100) + (flat1 >= 200);
            int idx0 = (flat0 >> 2) + s0 * (EPQ - 25);
            int idx1 = (flat1 >> 2) + s1 * (EPQ - 25);
            uint32_t a0 = EgS[rowbase + idx0];
            uint32_t a1 = EgS[rowbase + 8 * EPQ + idx0];
            uint32_t a2 = EgS[rowbase + idx1];
            uint32_t a3 = EgS[rowbase + 8 * EPQ + idx1];
            const uint32_t* bp = Bcur + (lane >> 2) * 8 + 2 * (lane & 3);
            #pragma unroll
            for (int nt = 0; nt < 13; ++nt) {
                uint2 bv = *reinterpret_cast<const uint2*>(bp + nt * 64);
                mma16n8k32s8(acc[nt], a0, a1, a2, a3, bv.x, bv.y);
            }
        }
        int Ts = LGG - g;
        int tA = t0 + wid * 16 + (lane >> 2);
        int tB = tA + 8;
        unsigned* pool = d_pooled + b * 300 + g * 100;
        #pragma unroll
        for (int nt = 0; nt < 13; ++nt) {
            float v0 = (tA < Ts) ? (float)acc[nt][0] * QINV : -1e30f;
            float v1 = (tA < Ts) ? (float)acc[nt][1] * QINV : -1e30f;
            float v2 = (tB < Ts) ? (float)acc[nt][2] * QINV : -1e30f;
            float v3 = (tB < Ts) ? (float)acc[nt][3] * QINV : -1e30f;
            v0 = fmaxf(v0, v2);
            v1 = fmaxf(v1, v3);
            #pragma unroll
            for (int off = 16; off >= 4; off >>= 1) {
                v0 = fmaxf(v0, __shfl_xor_sync(0xffffffffu, v0, off));
                v1 = fmaxf(v1, __shfl_xor_sync(0xffffffffu, v1, off));
            }
            if (lane < 4) {
                int f0 = nt * 8 + lane * 2;
                float r0v = fmaxf(v0 + sBias[g][f0], 0.f);
                float r1v = fmaxf(v1 + sBias[g][f0 + 1], 0.f);
                if (f0 < 100)     atomicMax(&pool[f0],     __float_as_uint(r0v));
                if (f0 + 1 < 100) atomicMax(&pool[f0 + 1], __float_as_uint(r1v));
            }
        }
    }
}

// ---------------- K6: fused scan + local + global -> d_combine -------------
__global__ void __launch_bounds__(256) k_tail(
    const int* __restrict__ ltext, const float* __restrict__ emb,
    const float* __restrict__ att2_w, const float* __restrict__ att2_b,
    const float* __restrict__ mf_w, const float* __restrict__ mf_b) {
    __shared__ int   toks[SCAN_KEEP];
    __shared__ float jflag[SCAN_KEEP];
    __shared__ float twr[DM];
    __shared__ float combine[200];
    __shared__ float ps[300];
    int b = blockIdx.x, tid = threadIdx.x;

    if (tid < SCAN_KEEP) {
        int p = SCAN_START + tid;
        toks[tid]  = ltext[b * LLEN + p + 2];
        jflag[tid] = (d_Tsum[b * LLEN + p + 2] > d_cmp[p]) ? 1.f : 0.f;
    }
    for (int u = tid; u < 300; u += 256)
        ps[u] = __uint_as_float(d_pooled[b * 300 + u]);
    __syncthreads();

    if (tid < DM) {
        const float r = 1.0f / 411.0f;
        float tw = 0.f;
        #pragma unroll 8
        for (int i = 0; i < SCAN_KEEP; ++i) {
            float e = emb[(long)toks[i] * DM + tid] * jflag[i];
            tw = (tw + e) * r;
        }
        twr[tid] = tw;
    } else if (tid >= 128 && tid < 228) {
        int f = tid - 128;
        float acc = mf_b[f];
        const float* wr = mf_w + f * 300;
        #pragma unroll 4
        for (int i = 0; i < 300; ++i) acc += ps[i] * wr[i];
        combine[100 + f] = acc;
    }
    __syncthreads();

    if (tid < DM) {
        float acc = att2_b[tid];
        const float* wr = att2_w + tid * DM;
        #pragma unroll 4
        for (int d = 0; d < DM; ++d) acc += twr[d] * wr[d];
        combine[tid] = acc;
    }
    __syncthreads();

    if (tid < 200) d_combine[b * 200 + tid] = combine[tid];
}

// ---------------- K7: fin GEMM, 128c x 16b tiles, grid (4,16) --------------
__global__ void __launch_bounds__(512) k_fin(const float* __restrict__ fw,
                                             const float* __restrict__ fb) {
    __shared__ float cs[16 * 100];
    int c0 = blockIdx.x * 128;
    int b0 = blockIdx.y * 16;
    int tid = threadIdx.x;
    int ci = tid & 127, bg = tid >> 7;
    int c = c0 + ci;
    bool cvalid = (c < 400);

    unsigned long long acc[4];
    #pragma unroll
    for (int i = 0; i < 4; ++i) acc[i] = 0ull;

    for (int p = 0; p < 2; ++p) {
        __syncthreads();
        for (int u = tid; u < 16 * 100; u += 512)
            cs[u] = d_combine[(b0 + u / 100) * 200 + p * 100 + (u % 100)];
        __syncthreads();
        if (cvalid) {
            const float* wr = fw + (long)c * 200 + p * 100;
            const float* hb = cs + bg * 4 * 100;
            for (int h = 0; h < 100; h += 2) {
                unsigned long long wv = *reinterpret_cast<const unsigned long long*>(wr + h);
                #pragma unroll
                for (int i = 0; i < 4; ++i) {
                    unsigned long long hv =
                        *reinterpret_cast<const unsigned long long*>(hb + i * 100 + h);
                    acc[i] = ffma2(wv, hv, acc[i]);
                }
            }
        }
    }
    float bias = cvalid ? fb[c] : 0.f;
    int chunkc = c >> 4;
    int p2 = ((c >> 1) & 7);
    p2 = (p2 < 4) ? 2 * p2 : 2 * (p2 - 4) + 1;
    #pragma unroll
    for (int i = 0; i < 4; ++i) {
        float hid = cvalid ? fmaxf(acc2_sum(acc[i]) + bias, 0.f) : 0.f;
        float hiv = __shfl_down_sync(0xffffffffu, hid, 1);
        if (cvalid && !(ci & 1)) {
            int bb = b0 + bg * 4 + i;
            d_hbf[((chunkc * 32 + (bb >> 3)) * 8 + (bb & 7)) * 8 + p2] =
                pack_bf16(hid, hiv);
        }
    }
}

// ---------------- K8: out = hidden @ fin2_w.T + b via bf16 MMA -------------
__global__ void __launch_bounds__(192) k_out_mma(const float* __restrict__ fb,
                                                 float* __restrict__ out) {
    __shared__ __align__(16) uint32_t sB[25 * 4 * 64];   // 25600 B
    __shared__ float sBias[96];
    int tid = threadIdx.x, lane = tid & 31, wid = tid >> 5;
    int c0 = blockIdx.x * 96;
    int b0 = blockIdx.y * 32;
    int bt0 = blockIdx.y * 4;

    if (tid < 96) {
        int c = c0 + tid;
        sBias[tid] = (c < NCLS) ? fb[c] : 0.f;
    }
    {
        uint32_t sbase = smem_u32p(sB);
        for (int i = tid; i < 1600; i += 192) {
            int c = i >> 6, rem = i & 63, btl = rem >> 4, j = rem & 15;
            cp_async16(sbase + (uint32_t)(((c * 4 + btl) * 64 + j * 4) * 4),
                       &d_hbf[(c * 32 + bt0 + btl) * 64 + j * 4]);
        }
        cp_commit();
    }
    cp_wait<0>();
    __syncthreads();

    float acc[4][4];
    #pragma unroll
    for (int nt = 0; nt < 4; ++nt)
        #pragma unroll
        for (int j = 0; j < 4; ++j) acc[nt][j] = 0.f;

    const uint32_t* arow = &d_w2bf[(long)(c0 + wid * 16 + (lane >> 2)) * 200
                                   + 2 * (lane & 3)];
    const uint32_t* bp = &sB[(lane >> 2) * 8 + 2 * (lane & 3)];

    uint2 pLo = *reinterpret_cast<const uint2*>(arow);
    uint2 pHi = *reinterpret_cast<const uint2*>(arow + 8 * 200);
    for (int c = 0; c < 25; ++c) {
        uint2 aLo = pLo, aHi = pHi;
        if (c + 1 < 25) {
            pLo = *reinterpret_cast<const uint2*>(arow + (c + 1) * 8);
            pHi = *reinterpret_cast<const uint2*>(arow + 8 * 200 + (c + 1) * 8);
        }
        const uint32_t* bc = bp + c * 256;
        #pragma unroll
        for (int nt = 0; nt < 4; ++nt) {
            uint2 bv = *reinterpret_cast<const uint2*>(bc + nt * 64);
            mma16n8k16bf(acc[nt], aLo.x, aHi.x, aLo.y, aHi.y, bv.x, bv.y);
        }
    }
    int crA = wid * 16 + (lane >> 2);
    int crB = crA + 8;
    int gcA = c0 + crA, gcB = c0 + crB;
    float biasA = sBias[crA], biasB = sBias[crB];
    #pragma unroll
    for (int nt = 0; nt < 4; ++nt) {
        int bcol = b0 + nt * 8 + 2 * (lane & 3);
        if (gcA < NCLS) {
            out[(long)bcol * NCLS + gcA]       = acc[nt][0] + biasA;
            out[(long)(bcol + 1) * NCLS + gcA] = acc[nt][1] + biasA;
        }
        if (gcB < NCLS) {
            out[(long)bcol * NCLS + gcB]       = acc[nt][2] + biasB;
            out[(long)(bcol + 1) * NCLS + gcB] = acc[nt][3] + biasB;
        }
    }
}

// ---------------- launcher ----------------
extern "C" void kernel_launch(void* const* d_in, const int* in_sizes, int n_in,
                              void* d_out, int out_size) {
    const int*   ltext  = (const int*)d_in[0];
    const int*   gtext  = (const int*)d_in[1];
    const float* emb    = (const float*)d_in[2];
    const float* att_w  = (const float*)d_in[3];
    const float* att_b  = (const float*)d_in[4];
    const float* att2_w = (const float*)d_in[5];
    const float* att2_b = (const float*)d_in[6];
    const float* c1w    = (const float*)d_in[7];
    const float* c1b    = (const float*)d_in[8];
    const float* c2w    = (const float*)d_in[9];
    const float* c2b    = (const float*)d_in[10];
    const float* c3w    = (const float*)d_in[11];
    const float* c3b    = (const float*)d_in[12];
    const float* mfw    = (const float*)d_in[13];
    const float* mfb    = (const float*)d_in[14];
    const float* finw   = (const float*)d_in[15];
    const float* finb   = (const float*)d_in[16];
    const float* f2w    = (const float*)d_in[17];
    const float* f2b    = (const float*)d_in[18];
    float* out = (float*)d_out;

    k_prep<<<PREP_BLKS + TOK_BLKS, 256>>>(c1w, c2w, c3w, f2w,
                                          ltext, emb, att_w, att_b);
    k_cmp<<<SCAN_KEEP, 256>>>();
    k_conv_mma<<<dim3(4, BB), 224>>>(gtext, emb, c1b, c2b, c3b);
    k_tail<<<BB, 256>>>(ltext, emb, att2_w, att2_b, mfw, mfb);
    k_fin<<<dim3(4, 16), 512>>>(finw, finb);
    k_out_mma<<<dim3(32, 8), 192>>>(f2b, out);
}